// round 12
// baseline (speedup 1.0000x reference)
#include <cuda_runtime.h>
#include <cuda_bf16.h>
#include <math.h>
#include <stdint.h>

// ---------------- constants ----------------
#define BB 32
#define EE 256
#define HH 1500
#define G4 6000
#define PP 496
#define Q1S 600
#define QS 300
#define EV1S 1000
#define EV2S 100
#define MPAIR (BB*PP)   // 15872
#define MNB 1024
#define G4P 6144
#define PTP 1024
#define NZL 6
#define KP_E 256
#define KP_Q1 608
#define KP_Q 320
#define KP_E2 1024
#define KP_H 1536

// ---------------- f32 scratch ----------------
__device__ float d_xp[(size_t)G4*MNB];
__device__ float d_h[2][BB*HH];
__device__ float d_cT[BB*HH];
__device__ float d_gpart6[NZL][G4P*BB];
__device__ float d_pt4[4][PTP*BB];
__device__ float d_ptT[EV1S*BB];
__device__ float d_q1beff[Q1S];
__device__ int   d_pi[PP], d_pj[PP];
__device__ float d_Aq[MNB*Q1S];
__device__ float d_Bq[MNB*Q1S];
__device__ float d_e2buf[MPAIR*EV2S];
__device__ unsigned g_bar;

// ---------------- bf16 hi/lo preconverted (zero-padded) ----------------
__device__ __nv_bfloat16 d_wih_h[6016*KP_E],  d_wih_l[6016*KP_E];
__device__ __nv_bfloat16 d_S_h[MNB*KP_E],     d_S_l[MNB*KP_E];
__device__ __nv_bfloat16 d_x_h[MNB*KP_E],     d_x_l[MNB*KP_E];
__device__ __nv_bfloat16 d_q1wA_h[640*KP_E],  d_q1wA_l[640*KP_E];
__device__ __nv_bfloat16 d_q1wB_h[640*KP_E],  d_q1wB_l[640*KP_E];
__device__ __nv_bfloat16 d_q2w_h[320*KP_Q1],  d_q2w_l[320*KP_Q1];
__device__ __nv_bfloat16 d_e1wH_h[1024*KP_H], d_e1wH_l[1024*KP_H];
__device__ __nv_bfloat16 d_e1wQ_h[1024*KP_Q], d_e1wQ_l[1024*KP_Q];
__device__ __nv_bfloat16 d_e2w_h[128*KP_E2],  d_e2w_l[128*KP_E2];
__device__ __nv_bfloat16 d_whh_h[(size_t)G4P*KP_H], d_whh_l[(size_t)G4P*KP_H];
__device__ __nv_bfloat16 d_q2o_h[(size_t)MPAIR*KP_Q], d_q2o_l[(size_t)MPAIR*KP_Q];
__device__ __nv_bfloat16 d_e1o_h[(size_t)MPAIR*KP_E2], d_e1o_l[(size_t)MPAIR*KP_E2];

// ---------------- helpers ----------------
__device__ __forceinline__ uint32_t smem_u32(const void* p) {
    uint32_t a;
    asm("{ .reg .u64 t; cvta.to.shared.u64 t, %1; cvt.u32.u64 %0, t; }" : "=r"(a) : "l"(p));
    return a;
}
__device__ __forceinline__ void ldsm4(uint32_t* r, uint32_t addr) {
    asm volatile("ldmatrix.sync.aligned.m8n8.x4.shared.b16 {%0,%1,%2,%3}, [%4];"
        : "=r"(r[0]), "=r"(r[1]), "=r"(r[2]), "=r"(r[3]) : "r"(addr));
}
__device__ __forceinline__ void ldsm2(uint32_t* r, uint32_t addr) {
    asm volatile("ldmatrix.sync.aligned.m8n8.x2.shared.b16 {%0,%1}, [%2];"
        : "=r"(r[0]), "=r"(r[1]) : "r"(addr));
}
__device__ __forceinline__ void mma16816(float* c, const uint32_t* a, const uint32_t* b) {
    asm volatile("mma.sync.aligned.m16n8k16.row.col.f32.bf16.bf16.f32 "
        "{%0,%1,%2,%3}, {%4,%5,%6,%7}, {%8,%9}, {%0,%1,%2,%3};"
        : "+f"(c[0]), "+f"(c[1]), "+f"(c[2]), "+f"(c[3])
        : "r"(a[0]), "r"(a[1]), "r"(a[2]), "r"(a[3]), "r"(b[0]), "r"(b[1]));
}
__device__ __forceinline__ void cpa16(uint32_t d, const void* s) {
    asm volatile("cp.async.cg.shared.global [%0], [%1], 16;" :: "r"(d), "l"(s));
}
#define CPA_COMMIT() asm volatile("cp.async.commit_group;" ::: "memory")
#define CPA_WAITN(n) asm volatile("cp.async.wait_group %0;" :: "n"(n) : "memory")

__device__ __forceinline__ void bsplit(float v, unsigned& h, unsigned& l) {
    __nv_bfloat16 bh = __float2bfloat16_rn(v);
    float r = v - __bfloat162float(bh);
    __nv_bfloat16 bl = __float2bfloat16_rn(r);
    h = (unsigned)__bfloat16_as_ushort(bh);
    l = (unsigned)__bfloat16_as_ushort(bl);
}
__device__ __forceinline__ void conv8(float4 a, float4 b, uint4& H, uint4& L) {
    unsigned h0,h1,h2,h3,h4,h5,h6,h7, l0,l1,l2,l3,l4,l5,l6,l7;
    bsplit(a.x,h0,l0); bsplit(a.y,h1,l1); bsplit(a.z,h2,l2); bsplit(a.w,h3,l3);
    bsplit(b.x,h4,l4); bsplit(b.y,h5,l5); bsplit(b.z,h6,l6); bsplit(b.w,h7,l7);
    H.x = h0 | (h1<<16); H.y = h2 | (h3<<16); H.z = h4 | (h5<<16); H.w = h6 | (h7<<16);
    L.x = l0 | (l1<<16); L.y = l2 | (l3<<16); L.z = l4 | (l5<<16); L.w = l6 | (l7<<16);
}

// ============================================================================
// tgemm512: 512 threads, BM=BN=128, 3-stage cp.async. Packed epilogue stores.
// ============================================================================
__global__ void __launch_bounds__(512) tgemm512(
    const __nv_bfloat16* __restrict__ Ah, const __nv_bfloat16* __restrict__ Al, int lakp,
    const __nv_bfloat16* __restrict__ Bh, const __nv_bfloat16* __restrict__ Bl, int lbkp,
    const float* __restrict__ bias_n, const float* __restrict__ rowt,
    float* __restrict__ Cf, __nv_bfloat16* __restrict__ Ch, __nv_bfloat16* __restrict__ Cl,
    int ldchl, int M, int Nn, int Kp, int relu)
{
    constexpr int ALOo = 10240, BHIo = 20480, BLOo = 30720;
    constexpr int STG = 40960;
    extern __shared__ char smem[];
    uint32_t sbase = smem_u32(smem);
    int tid = threadIdx.x, lane = tid & 31, wid = tid >> 5;
    int wm = wid & 3, wn = wid >> 2;
    int m0 = blockIdx.y * 128, n0 = blockIdx.x * 128;

    const char* src[4]; uint32_t dst[4];
    #pragma unroll
    for (int s = 0; s < 4; s++) {
        int g = tid + s * 512;
        int isB = (g >= 1024);
        int g1 = g - isB * 1024;
        int half = (g1 >= 512);
        int g2 = g1 - half * 512;
        int row = g2 >> 2, seg = g2 & 3;
        const __nv_bfloat16* base = isB ? (half ? Bl : Bh) : (half ? Al : Ah);
        int ld = isB ? lbkp : lakp;
        int r0 = isB ? n0 : m0;
        src[s] = (const char*)(base + (size_t)(r0 + row) * ld + seg * 8);
        dst[s] = (uint32_t)(isB * BHIo + half * ALOo + row * 80 + seg * 16);
    }
    auto prefetch = [&](int ik, int buf) {
        uint32_t bo = (uint32_t)(buf * STG);
        #pragma unroll
        for (int s = 0; s < 4; s++) cpa16(sbase + bo + dst[s], src[s] + (size_t)ik * 64);
    };

    uint32_t aoff[2], boff[4];
    #pragma unroll
    for (int mt = 0; mt < 2; mt++)
        aoff[mt] = (uint32_t)(((wm*32 + mt*16 + (lane & 15)) * 40 + ((lane >> 4) & 1) * 8) * 2);
    #pragma unroll
    for (int nt = 0; nt < 4; nt++)
        boff[nt] = (uint32_t)(((wn*32 + nt*8 + (lane & 7)) * 40 + ((lane >> 3) & 1) * 8) * 2);

    float acc[2][4][4];
    #pragma unroll
    for (int mt = 0; mt < 2; mt++)
        #pragma unroll
        for (int nt = 0; nt < 4; nt++)
            #pragma unroll
            for (int q = 0; q < 4; q++) acc[mt][nt][q] = 0.f;

    int nk = Kp >> 5;
    prefetch(0, 0); CPA_COMMIT();
    if (nk > 1) prefetch(1, 1);
    CPA_COMMIT();

    for (int i = 0; i < nk; i++) {
        if (i + 1 < nk) CPA_WAITN(1); else CPA_WAITN(0);
        __syncthreads();
        if (i + 2 < nk) prefetch(i + 2, (i + 2) % 3);
        CPA_COMMIT();
        uint32_t tb = sbase + (uint32_t)((i % 3) * STG);
        #pragma unroll
        for (int kh = 0; kh < 2; kh++) {
            uint32_t ah[2][4], al[2][4], bh[4][2], bl[4][2];
            #pragma unroll
            for (int mt = 0; mt < 2; mt++) {
                ldsm4(ah[mt], tb + aoff[mt] + kh*32);
                ldsm4(al[mt], tb + ALOo + aoff[mt] + kh*32);
            }
            #pragma unroll
            for (int nt = 0; nt < 4; nt++) {
                ldsm2(bh[nt], tb + BHIo + boff[nt] + kh*32);
                ldsm2(bl[nt], tb + BLOo + boff[nt] + kh*32);
            }
            #pragma unroll
            for (int mt = 0; mt < 2; mt++)
                #pragma unroll
                for (int nt = 0; nt < 4; nt++) {
                    mma16816(acc[mt][nt], ah[mt], bh[nt]);
                    mma16816(acc[mt][nt], ah[mt], bl[nt]);
                    mma16816(acc[mt][nt], al[mt], bh[nt]);
                }
        }
        __syncthreads();
    }

    // epilogue with packed stores
    #pragma unroll
    for (int mt = 0; mt < 2; mt++) {
        #pragma unroll
        for (int half = 0; half < 2; half++) {
            int gm = m0 + wm*32 + mt*16 + (lane >> 2) + half*8;
            if (gm >= M) continue;
            int bidx = gm / PP;
            #pragma unroll
            for (int nt = 0; nt < 4; nt++) {
                int gn = n0 + wn*32 + nt*8 + (lane & 3) * 2;   // always even
                float v0 = acc[mt][nt][half*2+0];
                float v1 = acc[mt][nt][half*2+1];
                bool ok0 = gn < Nn, ok1 = gn + 1 < Nn;
                if (bias_n) { if (ok0) v0 += bias_n[gn]; if (ok1) v1 += bias_n[gn+1]; }
                if (rowt)   { if (ok0) v0 += rowt[(size_t)gn*32 + bidx];
                              if (ok1) v1 += rowt[(size_t)(gn+1)*32 + bidx]; }
                if (relu)   { v0 = fmaxf(v0, 0.f); v1 = fmaxf(v1, 0.f); }
                if (Cf) {
                    if (ok0 && ok1) {
                        *(float2*)(Cf + (size_t)gm * Nn + gn) = make_float2(v0, v1);
                    } else {
                        if (ok0) Cf[(size_t)gm * Nn + gn] = v0;
                        if (ok1) Cf[(size_t)gm * Nn + gn + 1] = v1;
                    }
                } else if (gn < ldchl) {   // ldchl even => gn+1 < ldchl too
                    float w0 = ok0 ? v0 : 0.f, w1 = ok1 ? v1 : 0.f;
                    unsigned h0, l0, h1, l1;
                    bsplit(w0, h0, l0); bsplit(w1, h1, l1);
                    *(unsigned*)(Ch + (size_t)gm * ldchl + gn) = h0 | (h1 << 16);
                    *(unsigned*)(Cl + (size_t)gm * ldchl + gn) = l0 | (l1 << 16);
                }
            }
        }
    }
}

// ============================================================================
// tgemm2 (256-thread; q2 pair-fusion and pt). Packed epilogue stores.
// ============================================================================
template<int AMODE, int BPRE, int WR, int WC>
__global__ void __launch_bounds__(256, 2) tgemm2(
    const __nv_bfloat16* __restrict__ Ah, const __nv_bfloat16* __restrict__ Al, int lakp,
    const __nv_bfloat16* __restrict__ Bh, const __nv_bfloat16* __restrict__ Bl, int lbkp,
    const float* __restrict__ Bf, int ldbf,
    const float* __restrict__ bias_n, const float* __restrict__ rowt,
    float* __restrict__ Cf, __nv_bfloat16* __restrict__ Ch, __nv_bfloat16* __restrict__ Cl,
    int ldchl, int M, int Nn, int K, int relu, long zstride)
{
    constexpr int BM = WR*32, BN = WC*32;
    constexpr int ALOo = BM*80, BHIo = BM*160, BLOo = BM*160 + BN*80;
    constexpr int BUFSZ = (BM + BN) * 160;
    extern __shared__ char smem[];
    uint32_t sbase = smem_u32(smem);
    int tid = threadIdx.x, lane = tid & 31, wid = tid >> 5;
    int wm = wid % WR, wn = wid / WR;
    int m0 = blockIdx.y * BM, n0 = blockIdx.x * BN;

    int nk = (K + 31) >> 5;
    int chunk = (nk + gridDim.z - 1) / gridDim.z;
    int ks0 = blockIdx.z * chunk;
    int ks1 = min(nk, ks0 + chunk);
    float* Czf = Cf ? Cf + (size_t)blockIdx.z * zstride : nullptr;

    constexpr int NA = (AMODE == 1) ? (BM / 32) : 1;
    const char* asrc[NA];
    uint32_t adst[NA];
    if (AMODE == 1) {
        #pragma unroll
        for (int s = 0; s < NA; s++) {
            int g = tid + s * 256;
            int half = (g >= BM * 4);
            int g2 = g - half * BM * 4;
            int row = g2 >> 2, seg = g2 & 3;
            const __nv_bfloat16* base = half ? Al : Ah;
            asrc[s] = (const char*)(base + (size_t)(m0 + row) * lakp + seg * 8);
            adst[s] = half * ALOo + row * 80 + seg * 16;
        }
    }
    constexpr int NSEGA = BM / 64;
    int arow[NSEGA], asegc[NSEGA];
    const float *apf[NSEGA], *apf2[NSEGA];
    float4 sa0[NSEGA], sa1[NSEGA];
    const float4 f4z = make_float4(0.f, 0.f, 0.f, 0.f);
    if (AMODE == 2) {
        #pragma unroll
        for (int s = 0; s < NSEGA; s++) {
            int idx = tid + s * 256;
            arow[s] = idx >> 2; asegc[s] = idx & 3;
            int gm = m0 + arow[s];
            int b = gm / PP, p = gm - b * PP;
            apf[s]  = d_Aq + (size_t)(b * 32 + d_pi[p]) * Q1S;
            apf2[s] = d_Bq + (size_t)(b * 32 + d_pj[p]) * Q1S;
        }
    }
    constexpr int NB = (BPRE == 1) ? (BN / 32) : 1;
    const char* bsrc[NB];
    uint32_t bdst[NB];
    if (BPRE == 1) {
        #pragma unroll
        for (int s = 0; s < NB; s++) {
            int g = tid + s * 256;
            if (g < BN * 8) {
                int half = (g >= BN * 4);
                int g2 = g - half * BN * 4;
                int row = g2 >> 2, seg = g2 & 3;
                const __nv_bfloat16* base = half ? Bl : Bh;
                bsrc[s] = (const char*)(base + (size_t)(n0 + row) * lbkp + seg * 8);
                bdst[s] = BHIo + half * (BLOo - BHIo) + row * 80 + seg * 16;
            } else { bsrc[s] = nullptr; bdst[s] = 0; }
        }
    }
    bool bact = (tid < BN * 4);
    int brow = tid >> 2, bsegc = tid & 3;
    const float* bpf = (BPRE == 0) ? (Bf + (size_t)brow * ldbf) : nullptr;
    float4 sb0 = f4z, sb1 = f4z;

    auto cpa_pre = [&](int ik, uint32_t bufo) {
        if (AMODE == 1) {
            #pragma unroll
            for (int s = 0; s < NA; s++) cpa16(sbase + bufo + adst[s], asrc[s] + (size_t)ik * 64);
        }
        if (BPRE == 1) {
            #pragma unroll
            for (int s = 0; s < NB; s++)
                if (bsrc[s]) cpa16(sbase + bufo + bdst[s], bsrc[s] + (size_t)ik * 64);
        }
    };
    auto load_regs = [&](int ik) {
        int kg = ik * 32;
        if (AMODE == 2) {
            #pragma unroll
            for (int s = 0; s < NSEGA; s++) {
                int gk = kg + asegc[s] * 8;
                if (gk < K) {
                    float4 u = *(const float4*)(apf[s] + gk), v = *(const float4*)(apf2[s] + gk);
                    sa0[s] = make_float4(fmaxf(u.x+v.x,0.f), fmaxf(u.y+v.y,0.f),
                                         fmaxf(u.z+v.z,0.f), fmaxf(u.w+v.w,0.f));
                } else sa0[s] = f4z;
                if (gk + 4 < K) {
                    float4 u = *(const float4*)(apf[s] + gk + 4), v = *(const float4*)(apf2[s] + gk + 4);
                    sa1[s] = make_float4(fmaxf(u.x+v.x,0.f), fmaxf(u.y+v.y,0.f),
                                         fmaxf(u.z+v.z,0.f), fmaxf(u.w+v.w,0.f));
                } else sa1[s] = f4z;
            }
        }
        if (BPRE == 0 && bact) {
            int gk = kg + bsegc * 8;
            sb0 = (gk < K)     ? *(const float4*)(bpf + gk)     : f4z;
            sb1 = (gk + 4 < K) ? *(const float4*)(bpf + gk + 4) : f4z;
        }
    };
    auto conv_store = [&](char* buf) {
        if (AMODE == 2) {
            #pragma unroll
            for (int s = 0; s < NSEGA; s++) {
                uint4 H, L; conv8(sa0[s], sa1[s], H, L);
                *(uint4*)(buf + arow[s]*80 + asegc[s]*16) = H;
                *(uint4*)(buf + ALOo + arow[s]*80 + asegc[s]*16) = L;
            }
        }
        if (BPRE == 0 && bact) {
            uint4 H, L; conv8(sb0, sb1, H, L);
            *(uint4*)(buf + BHIo + brow*80 + bsegc*16) = H;
            *(uint4*)(buf + BLOo + brow*80 + bsegc*16) = L;
        }
    };

    uint32_t aoff[2], boff[4];
    #pragma unroll
    for (int mt = 0; mt < 2; mt++)
        aoff[mt] = (uint32_t)(((wm*32 + mt*16 + (lane & 15)) * 40 + ((lane >> 4) & 1) * 8) * 2);
    #pragma unroll
    for (int nt = 0; nt < 4; nt++)
        boff[nt] = (uint32_t)(((wn*32 + nt*8 + (lane & 7)) * 40 + ((lane >> 3) & 1) * 8) * 2);

    float acc[2][4][4];
    #pragma unroll
    for (int mt = 0; mt < 2; mt++)
        #pragma unroll
        for (int nt = 0; nt < 4; nt++)
            #pragma unroll
            for (int q = 0; q < 4; q++) acc[mt][nt][q] = 0.f;

    cpa_pre(ks0, 0); CPA_COMMIT();
    load_regs(ks0);
    conv_store(smem);
    for (int i = ks0; i < ks1; i++) {
        bool more = (i + 1 < ks1);
        if (more) { cpa_pre(i + 1, ((i + 1 - ks0) & 1) * BUFSZ); CPA_COMMIT(); load_regs(i + 1); }
        if (more) CPA_WAITN(1); else CPA_WAITN(0);
        __syncthreads();
        uint32_t tb = sbase + ((i - ks0) & 1) * BUFSZ;
        #pragma unroll
        for (int kh = 0; kh < 2; kh++) {
            uint32_t ah[2][4], al[2][4], bh[4][2], bl[4][2];
            #pragma unroll
            for (int mt = 0; mt < 2; mt++) {
                ldsm4(ah[mt], tb + aoff[mt] + kh*32);
                ldsm4(al[mt], tb + ALOo + aoff[mt] + kh*32);
            }
            #pragma unroll
            for (int nt = 0; nt < 4; nt++) {
                ldsm2(bh[nt], tb + BHIo + boff[nt] + kh*32);
                ldsm2(bl[nt], tb + BLOo + boff[nt] + kh*32);
            }
            #pragma unroll
            for (int mt = 0; mt < 2; mt++)
                #pragma unroll
                for (int nt = 0; nt < 4; nt++) {
                    mma16816(acc[mt][nt], ah[mt], bh[nt]);
                    mma16816(acc[mt][nt], ah[mt], bl[nt]);
                    mma16816(acc[mt][nt], al[mt], bh[nt]);
                }
        }
        if (more) conv_store(smem + ((i + 1 - ks0) & 1) * BUFSZ);
        __syncthreads();
    }

    #pragma unroll
    for (int mt = 0; mt < 2; mt++) {
        #pragma unroll
        for (int half = 0; half < 2; half++) {
            int gm = m0 + wm*32 + mt*16 + (lane >> 2) + half*8;
            if (gm >= M) continue;
            int bidx = gm / PP;
            #pragma unroll
            for (int nt = 0; nt < 4; nt++) {
                int gn = n0 + wn*32 + nt*8 + (lane & 3) * 2;
                float v0 = acc[mt][nt][half*2+0];
                float v1 = acc[mt][nt][half*2+1];
                bool ok0 = gn < Nn, ok1 = gn + 1 < Nn;
                if (bias_n) { if (ok0) v0 += bias_n[gn]; if (ok1) v1 += bias_n[gn+1]; }
                if (rowt)   { if (ok0) v0 += rowt[(size_t)gn*32 + bidx];
                              if (ok1) v1 += rowt[(size_t)(gn+1)*32 + bidx]; }
                if (relu)   { v0 = fmaxf(v0, 0.f); v1 = fmaxf(v1, 0.f); }
                if (Czf) {
                    if (ok0 && ok1) {
                        *(float2*)(Czf + (size_t)gm * Nn + gn) = make_float2(v0, v1);
                    } else {
                        if (ok0) Czf[(size_t)gm * Nn + gn] = v0;
                        if (ok1) Czf[(size_t)gm * Nn + gn + 1] = v1;
                    }
                } else if (gn < ldchl) {
                    float w0 = ok0 ? v0 : 0.f, w1 = ok1 ? v1 : 0.f;
                    unsigned h0, l0, h1, l1;
                    bsplit(w0, h0, l0); bsplit(w1, h1, l1);
                    *(unsigned*)(Ch + (size_t)gm * ldchl + gn) = h0 | (h1 << 16);
                    *(unsigned*)(Cl + (size_t)gm * ldchl + gn) = l0 | (l1 << 16);
                }
            }
        }
    }
}

// ============================================================================
// Persistent fused LSTM (144 CTAs, 32 steps).
// ============================================================================
__device__ __forceinline__ void gridbar(unsigned n) {
    __syncthreads();
    __threadfence();
    if (threadIdx.x == 0) {
        unsigned tk = atomicAdd(&g_bar, 1u);
        unsigned target = (tk / n + 1u) * n;
        while (atomicAdd(&g_bar, 0u) < target) { __nanosleep(64); }
    }
    __syncthreads();
}

__global__ void __launch_bounds__(256) k_lstm_all(
    const float* __restrict__ b_ih, const float* __restrict__ b_hh)
{
    constexpr int BM = 256, BN = 32;
    constexpr int ALOo = BM*80, BHIo = BM*160, BLOo = BM*160 + BN*80;
    constexpr int BUFSZ = (BM + BN) * 160;
    extern __shared__ char smem[];
    uint32_t sbase = smem_u32(smem);
    int tid = threadIdx.x, lane = tid & 31, wid = tid >> 5;
    int wm = wid;
    int bid = blockIdx.x;
    int z = bid % NZL, my = bid / NZL;
    int m0 = my * 256;
    const int nk = 47;
    int ks0 = z * 8, ks1 = min(nk, ks0 + 8);

    const char* asrc[8]; uint32_t adst[8];
    #pragma unroll
    for (int s = 0; s < 8; s++) {
        int g = tid + s * 256;
        int half = (g >= BM * 4);
        int g2 = g - half * BM * 4;
        int row = g2 >> 2, seg = g2 & 3;
        const __nv_bfloat16* base = half ? d_whh_l : d_whh_h;
        asrc[s] = (const char*)(base + (size_t)(m0 + row) * KP_H + seg * 8);
        adst[s] = half * ALOo + row * 80 + seg * 16;
    }
    bool bact = (tid < 128);
    int brow = tid >> 2, bsegc = tid & 3;
    const float4 f4z = make_float4(0.f,0.f,0.f,0.f);

    uint32_t aoff[2], boff[4];
    #pragma unroll
    for (int mt = 0; mt < 2; mt++)
        aoff[mt] = (uint32_t)(((wm*32 + mt*16 + (lane & 15)) * 40 + ((lane >> 4) & 1) * 8) * 2);
    #pragma unroll
    for (int nt = 0; nt < 4; nt++)
        boff[nt] = (uint32_t)(((nt*8 + (lane & 7)) * 40 + ((lane >> 3) & 1) * 8) * 2);

    float* gp = d_gpart6[z];

    for (int t = 0; t < 32; t++) {
        const float* hprev = d_h[t & 1];
        const float* bpf = hprev + (size_t)brow * HH;
        float4 sb0 = f4z, sb1 = f4z;

        auto cpa_pre = [&](int ik, uint32_t bufo) {
            #pragma unroll
            for (int s = 0; s < 8; s++) cpa16(sbase + bufo + adst[s], asrc[s] + (size_t)ik * 64);
        };
        auto load_b = [&](int ik) {
            if (!bact) return;
            int gk = ik * 32 + bsegc * 8;
            sb0 = (gk < HH)     ? __ldcg((const float4*)(bpf + gk))     : f4z;
            sb1 = (gk + 4 < HH) ? __ldcg((const float4*)(bpf + gk + 4)) : f4z;
        };
        auto store_b = [&](char* buf) {
            if (!bact) return;
            uint4 H, L; conv8(sb0, sb1, H, L);
            *(uint4*)(buf + BHIo + brow*80 + bsegc*16) = H;
            *(uint4*)(buf + BLOo + brow*80 + bsegc*16) = L;
        };

        float acc[2][4][4];
        #pragma unroll
        for (int mt = 0; mt < 2; mt++)
            #pragma unroll
            for (int nt = 0; nt < 4; nt++)
                #pragma unroll
                for (int q = 0; q < 4; q++) acc[mt][nt][q] = 0.f;

        cpa_pre(ks0, 0); CPA_COMMIT();
        load_b(ks0); store_b(smem);
        for (int i = ks0; i < ks1; i++) {
            bool more = (i + 1 < ks1);
            if (more) { cpa_pre(i + 1, ((i + 1 - ks0) & 1) * BUFSZ); CPA_COMMIT(); load_b(i + 1); }
            if (more) CPA_WAITN(1); else CPA_WAITN(0);
            __syncthreads();
            uint32_t tb = sbase + ((i - ks0) & 1) * BUFSZ;
            #pragma unroll
            for (int kh = 0; kh < 2; kh++) {
                uint32_t ah[2][4], al[2][4], bh[4][2], bl[4][2];
                #pragma unroll
                for (int mt = 0; mt < 2; mt++) {
                    ldsm4(ah[mt], tb + aoff[mt] + kh*32);
                    ldsm4(al[mt], tb + ALOo + aoff[mt] + kh*32);
                }
                #pragma unroll
                for (int nt = 0; nt < 4; nt++) {
                    ldsm2(bh[nt], tb + BHIo + boff[nt] + kh*32);
                    ldsm2(bl[nt], tb + BLOo + boff[nt] + kh*32);
                }
                #pragma unroll
                for (int mt = 0; mt < 2; mt++)
                    #pragma unroll
                    for (int nt = 0; nt < 4; nt++) {
                        mma16816(acc[mt][nt], ah[mt], bh[nt]);
                        mma16816(acc[mt][nt], ah[mt], bl[nt]);
                        mma16816(acc[mt][nt], al[mt], bh[nt]);
                    }
            }
            if (more) store_b(smem + ((i + 1 - ks0) & 1) * BUFSZ);
            __syncthreads();
        }

        #pragma unroll
        for (int mt = 0; mt < 2; mt++)
            #pragma unroll
            for (int half = 0; half < 2; half++) {
                int gm = m0 + wm*32 + mt*16 + (lane >> 2) + half*8;
                #pragma unroll
                for (int nt = 0; nt < 4; nt++) {
                    int gn = nt*8 + (lane & 3) * 2;
                    *(float2*)(gp + (size_t)gm * 32 + gn) =
                        make_float2(acc[mt][nt][half*2+0], acc[mt][nt][half*2+1]);
                }
            }

        gridbar(144);

        for (int e = bid * 256 + tid; e < BB * HH; e += 144 * 256) {
            int j = e >> 5, b = e & 31;
            float g[4];
            #pragma unroll
            for (int gg = 0; gg < 4; gg++) {
                int r = gg * HH + j;
                float v = d_xp[(size_t)r * MNB + t * 32 + b] + b_ih[r] + b_hh[r];
                #pragma unroll
                for (int zz = 0; zz < NZL; zz++) v += __ldcg(&d_gpart6[zz][(size_t)r * 32 + b]);
                g[gg] = v;
            }
            float ci = 1.f / (1.f + expf(-g[0]));
            float cf = 1.f / (1.f + expf(-g[1]));
            float cg = tanhf(g[2]);
            float co = 1.f / (1.f + expf(-g[3]));
            float cn = cf * d_cT[e] + ci * cg;
            d_cT[e] = cn;
            d_h[(t + 1) & 1][b * HH + j] = co * tanhf(cn);
        }

        gridbar(144);
    }
}

// ---------------- sort ----------------
__global__ void k_sort(const float* __restrict__ x) {
    int tid = blockIdx.x * blockDim.x + threadIdx.x;
    int b = tid >> 8, e = tid & 255;
    float v[32];
    #pragma unroll
    for (int t = 0; t < 32; t++) v[t] = x[(b * 32 + t) * EE + e];
    for (int a = 1; a < 32; a++) {
        float key = v[a];
        int c = a - 1;
        while (c >= 0 && v[c] > key) { v[c + 1] = v[c]; c--; }
        v[c + 1] = key;
    }
    #pragma unroll
    for (int t = 0; t < 32; t++) {
        unsigned hh, ll; bsplit(v[t], hh, ll);
        size_t idx = (size_t)(t * 32 + b) * KP_E + e;
        d_S_h[idx] = __ushort_as_bfloat16((unsigned short)hh);
        d_S_l[idx] = __ushort_as_bfloat16((unsigned short)ll);
    }
}

// ---------------- vectorized f32 -> hi/lo padded converter ----------------
__global__ void k_conv(const float* __restrict__ src, int ld, int Mr, int Kr,
                       __nv_bfloat16* __restrict__ h, __nv_bfloat16* __restrict__ l,
                       int Kp, long total)
{
    long idx8 = ((long)blockIdx.x * 256 + threadIdx.x) * 8;
    if (idx8 >= total) return;
    int r = (int)(idx8 / Kp), c = (int)(idx8 - (long)r * Kp);
    uint4 H, L;
    if (r < Mr && c + 7 < Kr) {
        const float* p = src + (size_t)r * ld + c;
        conv8(*(const float4*)p, *(const float4*)(p + 4), H, L);
    } else {
        float v[8];
        #pragma unroll
        for (int i = 0; i < 8; i++) {
            int cc = c + i;
            v[i] = (r < Mr && cc < Kr) ? src[(size_t)r * ld + cc] : 0.f;
        }
        conv8(make_float4(v[0],v[1],v[2],v[3]), make_float4(v[4],v[5],v[6],v[7]), H, L);
    }
    *(uint4*)(h + idx8) = H;
    *(uint4*)(l + idx8) = L;
}

// ---------------- init ----------------
__global__ void k_init(const float* __restrict__ q1_w, const float* __restrict__ q1_b) {
    int idx = blockIdx.x * blockDim.x + threadIdx.x;
    if (idx < PP) {
        int p = idx, i = 0, cnt = 31;
        while (p >= cnt) { p -= cnt; i++; cnt--; }
        d_pi[idx] = i; d_pj[idx] = i + 1 + p;
    } else if (idx < PP + Q1S) {
        int o = idx - PP;
        float s = q1_b[o];
        for (int d = 1; d < 2 * EE; d += 2) s += q1_w[o * (2 * EE) + d];
        d_q1beff[o] = s;
    } else {
        int zz = idx - (PP + Q1S);
        if (zz < BB * HH)           d_h[0][zz] = 0.f;
        else if (zz < 2 * BB * HH)  d_h[1][zz - BB * HH] = 0.f;
        else if (zz < 3 * BB * HH)  d_cT[zz - 2 * BB * HH] = 0.f;
    }
}

// ---------------- pt combine ----------------
__global__ void k_ptcomb(const float* __restrict__ e1_b) {
    int idx = blockIdx.x * blockDim.x + threadIdx.x;
    if (idx >= EV1S * BB) return;
    int n = idx >> 5;
    float v = e1_b[n];
    #pragma unroll
    for (int z = 0; z < 4; z++) v += d_pt4[z][idx];
    d_ptT[idx] = v;
}

// ---------------- tail: e3 + e4 ----------------
__global__ void k_tail(const float* __restrict__ e3w, const float* __restrict__ e3b,
                       const float* __restrict__ e4w, const float* __restrict__ e4b,
                       float* __restrict__ out)
{
    __shared__ float s2[64][101];
    __shared__ float sw[10][100];
    __shared__ float sb[10], s4[10];
    __shared__ float s4b;
    int m0 = blockIdx.x * 64;
    int tid = threadIdx.x;
    for (int l = 0; l < 100; l++) {
        int idx = tid + l * 64;
        s2[idx / 100][idx % 100] = d_e2buf[(size_t)m0 * EV2S + idx];
    }
    if (tid < 10) { sb[tid] = e3b[tid]; s4[tid] = e4w[tid]; }
    if (tid == 0) s4b = e4b[0];
    for (int l = tid; l < 1000; l += 64) sw[l / 100][l % 100] = e3w[l];
    __syncthreads();
    float acc = s4b;
    #pragma unroll
    for (int g = 0; g < 10; g++) {
        float a = sb[g];
        #pragma unroll 4
        for (int k = 0; k < 100; k++) a = fmaf(s2[tid][k], sw[g][k], a);
        acc = fmaf(fmaxf(a, 0.f), s4[g], acc);
    }
    out[m0 + tid] = fmaxf(acc, 0.f);
}

// ---------------- launch ----------------
#define SM42 ((128+64)*160*2)
#define SM81 ((256+32)*160*2)
#define SM512 (40960*3)

extern "C" void kernel_launch(void* const* d_in, const int* in_sizes, int n_in,
                              void* d_out, int out_size)
{
    const float* x    = (const float*)d_in[0];
    const float* w_ih = (const float*)d_in[1];
    const float* w_hh = (const float*)d_in[2];
    const float* b_ih = (const float*)d_in[3];
    const float* b_hh = (const float*)d_in[4];
    const float* q1_w = (const float*)d_in[5];
    const float* q1_b = (const float*)d_in[6];
    const float* q2_w = (const float*)d_in[7];
    const float* q2_b = (const float*)d_in[8];
    const float* e1_w = (const float*)d_in[9];
    const float* e1_b = (const float*)d_in[10];
    const float* e2_w = (const float*)d_in[11];
    const float* e2_b = (const float*)d_in[12];
    const float* e3_w = (const float*)d_in[13];
    const float* e3_b = (const float*)d_in[14];
    const float* e4_w = (const float*)d_in[15];
    const float* e4_b = (const float*)d_in[16];
    float* out = (float*)d_out;

    static cudaStream_t s2s = nullptr;
    static cudaEvent_t evFork = nullptr, evJoin = nullptr, evW = nullptr;
    static bool inited = false;
    if (!inited) {
        cudaStreamCreateWithFlags(&s2s, cudaStreamNonBlocking);
        cudaEventCreateWithFlags(&evFork, cudaEventDisableTiming);
        cudaEventCreateWithFlags(&evJoin, cudaEventDisableTiming);
        cudaEventCreateWithFlags(&evW,    cudaEventDisableTiming);
        cudaFuncSetAttribute((const void*)tgemm512,        cudaFuncAttributeMaxDynamicSharedMemorySize, SM512);
        cudaFuncSetAttribute((const void*)tgemm2<2,1,4,2>, cudaFuncAttributeMaxDynamicSharedMemorySize, SM42);
        cudaFuncSetAttribute((const void*)tgemm2<1,0,8,1>, cudaFuncAttributeMaxDynamicSharedMemorySize, SM81);
        cudaFuncSetAttribute((const void*)k_lstm_all,      cudaFuncAttributeMaxDynamicSharedMemorySize, SM81);
        inited = true;
    }

    float *pXp, *pH0, *pPt4, *pPt, *pQb, *pAq, *pBq, *pE2;
    __nv_bfloat16 *pWih_h,*pWih_l,*pS_h,*pS_l,*pX_h,*pX_l,*pQ1A_h,*pQ1A_l,*pQ1B_h,*pQ1B_l;
    __nv_bfloat16 *pQ2w_h,*pQ2w_l,*pE1H_h,*pE1H_l,*pE1Q_h,*pE1Q_l,*pE2w_h,*pE2w_l;
    __nv_bfloat16 *pWhh_h,*pWhh_l,*pQ2o_h,*pQ2o_l,*pE1o_h,*pE1o_l;
    cudaGetSymbolAddress((void**)&pXp,  d_xp);
    cudaGetSymbolAddress((void**)&pH0,  d_h);
    cudaGetSymbolAddress((void**)&pPt4, d_pt4);
    cudaGetSymbolAddress((void**)&pPt,  d_ptT);
    cudaGetSymbolAddress((void**)&pQb,  d_q1beff);
    cudaGetSymbolAddress((void**)&pAq,  d_Aq);
    cudaGetSymbolAddress((void**)&pBq,  d_Bq);
    cudaGetSymbolAddress((void**)&pE2,  d_e2buf);
    cudaGetSymbolAddress((void**)&pWih_h, d_wih_h); cudaGetSymbolAddress((void**)&pWih_l, d_wih_l);
    cudaGetSymbolAddress((void**)&pS_h,  d_S_h);    cudaGetSymbolAddress((void**)&pS_l,  d_S_l);
    cudaGetSymbolAddress((void**)&pX_h,  d_x_h);    cudaGetSymbolAddress((void**)&pX_l,  d_x_l);
    cudaGetSymbolAddress((void**)&pQ1A_h, d_q1wA_h); cudaGetSymbolAddress((void**)&pQ1A_l, d_q1wA_l);
    cudaGetSymbolAddress((void**)&pQ1B_h, d_q1wB_h); cudaGetSymbolAddress((void**)&pQ1B_l, d_q1wB_l);
    cudaGetSymbolAddress((void**)&pQ2w_h, d_q2w_h);  cudaGetSymbolAddress((void**)&pQ2w_l, d_q2w_l);
    cudaGetSymbolAddress((void**)&pE1H_h, d_e1wH_h); cudaGetSymbolAddress((void**)&pE1H_l, d_e1wH_l);
    cudaGetSymbolAddress((void**)&pE1Q_h, d_e1wQ_h); cudaGetSymbolAddress((void**)&pE1Q_l, d_e1wQ_l);
    cudaGetSymbolAddress((void**)&pE2w_h, d_e2w_h);  cudaGetSymbolAddress((void**)&pE2w_l, d_e2w_l);
    cudaGetSymbolAddress((void**)&pWhh_h, d_whh_h);  cudaGetSymbolAddress((void**)&pWhh_l, d_whh_l);
    cudaGetSymbolAddress((void**)&pQ2o_h, d_q2o_h);  cudaGetSymbolAddress((void**)&pQ2o_l, d_q2o_l);
    cudaGetSymbolAddress((void**)&pE1o_h, d_e1o_h);  cudaGetSymbolAddress((void**)&pE1o_l, d_e1o_l);

    // ---- main: sort + init ----
    k_sort<<<32, 256>>>(x);
    k_init<<<(PP + Q1S + 3 * BB * HH + 255) / 256, 256>>>(q1_w, q1_b);

    cudaEventRecord(evFork, 0);
    cudaStreamWaitEvent(s2s, evFork, 0);

    // ---- side stream: whh conv first (LSTM dep), then pair chain + e-weight convs ----
    k_conv<<<(int)(((long)G4P*KP_H/8 + 255)/256), 256, 0, s2s>>>(w_hh, HH, G4, HH, pWhh_h, pWhh_l, KP_H, (long)G4P*KP_H);
    cudaEventRecord(evW, s2s);
    k_conv<<<(int)(((long)MNB*KP_E/8 + 255)/256), 256, 0, s2s>>>(x, EE, MNB, EE, pX_h, pX_l, KP_E, (long)MNB*KP_E);
    k_conv<<<(int)(((long)640*KP_E/8 + 255)/256), 256, 0, s2s>>>(q1_w, 2*EE, Q1S, EE, pQ1A_h, pQ1A_l, KP_E, (long)640*KP_E);
    k_conv<<<(int)(((long)640*KP_E/8 + 255)/256), 256, 0, s2s>>>(q1_w+EE, 2*EE, Q1S, EE, pQ1B_h, pQ1B_l, KP_E, (long)640*KP_E);
    k_conv<<<(int)(((long)320*KP_Q1/8 + 255)/256), 256, 0, s2s>>>(q2_w, Q1S, QS, Q1S, pQ2w_h, pQ2w_l, KP_Q1, (long)320*KP_Q1);
    k_conv<<<(int)(((long)1024*KP_H/8 + 255)/256), 256, 0, s2s>>>(e1_w, HH+QS, EV1S, HH, pE1H_h, pE1H_l, KP_H, (long)1024*KP_H);
    k_conv<<<(int)(((long)1024*KP_Q/8 + 255)/256), 256, 0, s2s>>>(e1_w+HH, HH+QS, EV1S, QS, pE1Q_h, pE1Q_l, KP_Q, (long)1024*KP_Q);
    k_conv<<<(int)(((long)128*KP_E2/8 + 255)/256), 256, 0, s2s>>>(e2_w, EV1S, EV2S, EV1S, pE2w_h, pE2w_l, KP_E2, (long)128*KP_E2);
    tgemm512<<<dim3(5, 8), 512, SM512, s2s>>>(
        pX_h, pX_l, KP_E, pQ1A_h, pQ1A_l, KP_E,
        pQb, nullptr, pAq, nullptr, nullptr, 0, MNB, Q1S, KP_E, 0);
    tgemm512<<<dim3(5, 8), 512, SM512, s2s>>>(
        pX_h, pX_l, KP_E, pQ1B_h, pQ1B_l, KP_E,
        nullptr, nullptr, pBq, nullptr, nullptr, 0, MNB, Q1S, KP_E, 0);
    tgemm2<2,1,4,2><<<dim3(5, 124, 1), 256, SM42, s2s>>>(
        nullptr, nullptr, 0, pQ2w_h, pQ2w_l, KP_Q1, nullptr, 0,
        q2_b, nullptr, nullptr, pQ2o_h, pQ2o_l, KP_Q, MPAIR, QS, Q1S, 1, 0);
    cudaEventRecord(evJoin, s2s);

    // ---- main: wih conv + xp + LSTM ----
    k_conv<<<(int)(((long)6016*KP_E/8 + 255)/256), 256>>>(w_ih, EE, G4, EE, pWih_h, pWih_l, KP_E, (long)6016*KP_E);
    tgemm512<<<dim3(8, 47), 512, SM512>>>(
        pWih_h, pWih_l, KP_E, pS_h, pS_l, KP_E,
        nullptr, nullptr, pXp, nullptr, nullptr, 0, G4, MNB, KP_E, 0);

    cudaStreamWaitEvent(0, evW, 0);
    k_lstm_all<<<144, 256, SM81>>>(b_ih, b_hh);

    // join side chain, then pt + evaluator chain
    cudaStreamWaitEvent(0, evJoin, 0);

    tgemm2<1,0,8,1><<<dim3(1, 4, 4), 256, SM81>>>(
        pE1H_h, pE1H_l, KP_H, nullptr, nullptr, 0, pH0, HH,
        nullptr, nullptr, pPt4, nullptr, nullptr, 0, EV1S, BB, HH, 0, (long)PTP * BB);
    k_ptcomb<<<(EV1S * BB + 255) / 256, 256>>>(e1_b);

    tgemm512<<<dim3(8, 124), 512, SM512>>>(
        pQ2o_h, pQ2o_l, KP_Q, pE1Q_h, pE1Q_l, KP_Q,
        nullptr, pPt, nullptr, pE1o_h, pE1o_l, KP_E2, MPAIR, EV1S, KP_Q, 1);

    tgemm512<<<dim3(1, 124), 512, SM512>>>(
        pE1o_h, pE1o_l, KP_E2, pE2w_h, pE2w_l, KP_E2,
        e2_b, nullptr, pE2, nullptr, nullptr, 0, MPAIR, EV2S, KP_E2, 1);

    k_tail<<<MPAIR / 64, 64>>>(e3_w, e3_b, e4_w, e4_b, out);
}

// round 13
// speedup vs baseline: 1.1974x; 1.1974x over previous
#include <cuda_runtime.h>
#include <cuda_bf16.h>
#include <math.h>
#include <stdint.h>

// ---------------- constants ----------------
#define BB 32
#define EE 256
#define HH 1500
#define G4 6000
#define PP 496
#define Q1S 600
#define QS 300
#define EV1S 1000
#define EV2S 100
#define MPAIR (BB*PP)   // 15872
#define MNB 1024
#define G4P 6144
#define PTP 1024
#define NZL 6
#define KP_E 256
#define KP_Q1 608
#define KP_Q 320
#define KP_E2 1024
#define KP_H 1536

// ---------------- f32 scratch ----------------
__device__ float d_xp[(size_t)G4*MNB];
__device__ float d_h[2][BB*HH];
__device__ float d_cT[BB*HH];
__device__ float d_gpart6[NZL][G4P*BB];
__device__ float d_pt4[4][PTP*BB];
__device__ float d_ptT[EV1S*BB];
__device__ float d_q1beff[Q1S];
__device__ int   d_pi[PP], d_pj[PP];
__device__ float d_Aq[MNB*Q1S];
__device__ float d_Bq[MNB*Q1S];
__device__ float d_e2buf[MPAIR*EV2S];
__device__ unsigned g_bar;

// ---------------- bf16 hi/lo preconverted (zero-padded) ----------------
__device__ __nv_bfloat16 d_wih_h[6016*KP_E],  d_wih_l[6016*KP_E];
__device__ __nv_bfloat16 d_S_h[MNB*KP_E],     d_S_l[MNB*KP_E];
__device__ __nv_bfloat16 d_x_h[MNB*KP_E],     d_x_l[MNB*KP_E];
__device__ __nv_bfloat16 d_q1wA_h[640*KP_E],  d_q1wA_l[640*KP_E];
__device__ __nv_bfloat16 d_q1wB_h[640*KP_E],  d_q1wB_l[640*KP_E];
__device__ __nv_bfloat16 d_q2w_h[320*KP_Q1],  d_q2w_l[320*KP_Q1];
__device__ __nv_bfloat16 d_e1wH_h[1024*KP_H], d_e1wH_l[1024*KP_H];
__device__ __nv_bfloat16 d_e1wQ_h[1024*KP_Q], d_e1wQ_l[1024*KP_Q];
__device__ __nv_bfloat16 d_e2w_h[128*KP_E2],  d_e2w_l[128*KP_E2];
__device__ __nv_bfloat16 d_whh_h[(size_t)G4P*KP_H], d_whh_l[(size_t)G4P*KP_H];
__device__ __nv_bfloat16 d_q2o_h[(size_t)MPAIR*KP_Q], d_q2o_l[(size_t)MPAIR*KP_Q];
__device__ __nv_bfloat16 d_e1o_h[(size_t)MPAIR*KP_E2], d_e1o_l[(size_t)MPAIR*KP_E2];

// ---------------- helpers ----------------
__device__ __forceinline__ uint32_t smem_u32(const void* p) {
    uint32_t a;
    asm("{ .reg .u64 t; cvta.to.shared.u64 t, %1; cvt.u32.u64 %0, t; }" : "=r"(a) : "l"(p));
    return a;
}
__device__ __forceinline__ void ldsm4(uint32_t* r, uint32_t addr) {
    asm volatile("ldmatrix.sync.aligned.m8n8.x4.shared.b16 {%0,%1,%2,%3}, [%4];"
        : "=r"(r[0]), "=r"(r[1]), "=r"(r[2]), "=r"(r[3]) : "r"(addr));
}
__device__ __forceinline__ void ldsm2(uint32_t* r, uint32_t addr) {
    asm volatile("ldmatrix.sync.aligned.m8n8.x2.shared.b16 {%0,%1}, [%2];"
        : "=r"(r[0]), "=r"(r[1]) : "r"(addr));
}
__device__ __forceinline__ void mma16816(float* c, const uint32_t* a, const uint32_t* b) {
    asm volatile("mma.sync.aligned.m16n8k16.row.col.f32.bf16.bf16.f32 "
        "{%0,%1,%2,%3}, {%4,%5,%6,%7}, {%8,%9}, {%0,%1,%2,%3};"
        : "+f"(c[0]), "+f"(c[1]), "+f"(c[2]), "+f"(c[3])
        : "r"(a[0]), "r"(a[1]), "r"(a[2]), "r"(a[3]), "r"(b[0]), "r"(b[1]));
}
__device__ __forceinline__ void cpa16(uint32_t d, const void* s) {
    asm volatile("cp.async.cg.shared.global [%0], [%1], 16;" :: "r"(d), "l"(s));
}
#define CPA_COMMIT() asm volatile("cp.async.commit_group;" ::: "memory")
#define CPA_WAITN(n) asm volatile("cp.async.wait_group %0;" :: "n"(n) : "memory")

__device__ __forceinline__ void bsplit(float v, unsigned& h, unsigned& l) {
    __nv_bfloat16 bh = __float2bfloat16_rn(v);
    float r = v - __bfloat162float(bh);
    __nv_bfloat16 bl = __float2bfloat16_rn(r);
    h = (unsigned)__bfloat16_as_ushort(bh);
    l = (unsigned)__bfloat16_as_ushort(bl);
}
__device__ __forceinline__ void conv8(float4 a, float4 b, uint4& H, uint4& L) {
    unsigned h0,h1,h2,h3,h4,h5,h6,h7, l0,l1,l2,l3,l4,l5,l6,l7;
    bsplit(a.x,h0,l0); bsplit(a.y,h1,l1); bsplit(a.z,h2,l2); bsplit(a.w,h3,l3);
    bsplit(b.x,h4,l4); bsplit(b.y,h5,l5); bsplit(b.z,h6,l6); bsplit(b.w,h7,l7);
    H.x = h0 | (h1<<16); H.y = h2 | (h3<<16); H.z = h4 | (h5<<16); H.w = h6 | (h7<<16);
    L.x = l0 | (l1<<16); L.y = l2 | (l3<<16); L.z = l4 | (l5<<16); L.w = l6 | (l7<<16);
}

// ============================================================================
// tgemm512: 512 threads, BM=BN=128, 3-stage cp.async. Packed epilogue stores.
// ============================================================================
__global__ void __launch_bounds__(512) tgemm512(
    const __nv_bfloat16* __restrict__ Ah, const __nv_bfloat16* __restrict__ Al, int lakp,
    const __nv_bfloat16* __restrict__ Bh, const __nv_bfloat16* __restrict__ Bl, int lbkp,
    const float* __restrict__ bias_n, const float* __restrict__ rowt,
    float* __restrict__ Cf, __nv_bfloat16* __restrict__ Ch, __nv_bfloat16* __restrict__ Cl,
    int ldchl, int M, int Nn, int Kp, int relu)
{
    constexpr int ALOo = 10240, BHIo = 20480, BLOo = 30720;
    constexpr int STG = 40960;
    extern __shared__ char smem[];
    uint32_t sbase = smem_u32(smem);
    int tid = threadIdx.x, lane = tid & 31, wid = tid >> 5;
    int wm = wid & 3, wn = wid >> 2;
    int m0 = blockIdx.y * 128, n0 = blockIdx.x * 128;

    const char* src[4]; uint32_t dst[4];
    #pragma unroll
    for (int s = 0; s < 4; s++) {
        int g = tid + s * 512;
        int isB = (g >= 1024);
        int g1 = g - isB * 1024;
        int half = (g1 >= 512);
        int g2 = g1 - half * 512;
        int row = g2 >> 2, seg = g2 & 3;
        const __nv_bfloat16* base = isB ? (half ? Bl : Bh) : (half ? Al : Ah);
        int ld = isB ? lbkp : lakp;
        int r0 = isB ? n0 : m0;
        src[s] = (const char*)(base + (size_t)(r0 + row) * ld + seg * 8);
        dst[s] = (uint32_t)(isB * BHIo + half * ALOo + row * 80 + seg * 16);
    }
    auto prefetch = [&](int ik, int buf) {
        uint32_t bo = (uint32_t)(buf * STG);
        #pragma unroll
        for (int s = 0; s < 4; s++) cpa16(sbase + bo + dst[s], src[s] + (size_t)ik * 64);
    };

    uint32_t aoff[2], boff[4];
    #pragma unroll
    for (int mt = 0; mt < 2; mt++)
        aoff[mt] = (uint32_t)(((wm*32 + mt*16 + (lane & 15)) * 40 + ((lane >> 4) & 1) * 8) * 2);
    #pragma unroll
    for (int nt = 0; nt < 4; nt++)
        boff[nt] = (uint32_t)(((wn*32 + nt*8 + (lane & 7)) * 40 + ((lane >> 3) & 1) * 8) * 2);

    float acc[2][4][4];
    #pragma unroll
    for (int mt = 0; mt < 2; mt++)
        #pragma unroll
        for (int nt = 0; nt < 4; nt++)
            #pragma unroll
            for (int q = 0; q < 4; q++) acc[mt][nt][q] = 0.f;

    int nk = Kp >> 5;
    prefetch(0, 0); CPA_COMMIT();
    if (nk > 1) prefetch(1, 1);
    CPA_COMMIT();

    for (int i = 0; i < nk; i++) {
        if (i + 1 < nk) CPA_WAITN(1); else CPA_WAITN(0);
        __syncthreads();
        if (i + 2 < nk) prefetch(i + 2, (i + 2) % 3);
        CPA_COMMIT();
        uint32_t tb = sbase + (uint32_t)((i % 3) * STG);
        #pragma unroll
        for (int kh = 0; kh < 2; kh++) {
            uint32_t ah[2][4], al[2][4], bh[4][2], bl[4][2];
            #pragma unroll
            for (int mt = 0; mt < 2; mt++) {
                ldsm4(ah[mt], tb + aoff[mt] + kh*32);
                ldsm4(al[mt], tb + ALOo + aoff[mt] + kh*32);
            }
            #pragma unroll
            for (int nt = 0; nt < 4; nt++) {
                ldsm2(bh[nt], tb + BHIo + boff[nt] + kh*32);
                ldsm2(bl[nt], tb + BLOo + boff[nt] + kh*32);
            }
            #pragma unroll
            for (int mt = 0; mt < 2; mt++)
                #pragma unroll
                for (int nt = 0; nt < 4; nt++) {
                    mma16816(acc[mt][nt], ah[mt], bh[nt]);
                    mma16816(acc[mt][nt], ah[mt], bl[nt]);
                    mma16816(acc[mt][nt], al[mt], bh[nt]);
                }
        }
        __syncthreads();
    }

    // epilogue with packed stores
    #pragma unroll
    for (int mt = 0; mt < 2; mt++) {
        #pragma unroll
        for (int half = 0; half < 2; half++) {
            int gm = m0 + wm*32 + mt*16 + (lane >> 2) + half*8;
            if (gm >= M) continue;
            int bidx = gm / PP;
            #pragma unroll
            for (int nt = 0; nt < 4; nt++) {
                int gn = n0 + wn*32 + nt*8 + (lane & 3) * 2;   // always even
                float v0 = acc[mt][nt][half*2+0];
                float v1 = acc[mt][nt][half*2+1];
                bool ok0 = gn < Nn, ok1 = gn + 1 < Nn;
                if (bias_n) { if (ok0) v0 += bias_n[gn]; if (ok1) v1 += bias_n[gn+1]; }
                if (rowt)   { if (ok0) v0 += rowt[(size_t)gn*32 + bidx];
                              if (ok1) v1 += rowt[(size_t)(gn+1)*32 + bidx]; }
                if (relu)   { v0 = fmaxf(v0, 0.f); v1 = fmaxf(v1, 0.f); }
                if (Cf) {
                    if (ok0 && ok1) {
                        *(float2*)(Cf + (size_t)gm * Nn + gn) = make_float2(v0, v1);
                    } else {
                        if (ok0) Cf[(size_t)gm * Nn + gn] = v0;
                        if (ok1) Cf[(size_t)gm * Nn + gn + 1] = v1;
                    }
                } else if (gn < ldchl) {
                    float w0 = ok0 ? v0 : 0.f, w1 = ok1 ? v1 : 0.f;
                    unsigned h0, l0, h1, l1;
                    bsplit(w0, h0, l0); bsplit(w1, h1, l1);
                    *(unsigned*)(Ch + (size_t)gm * ldchl + gn) = h0 | (h1 << 16);
                    *(unsigned*)(Cl + (size_t)gm * ldchl + gn) = l0 | (l1 << 16);
                }
            }
        }
    }
}

// ============================================================================
// tgemm2 (256-thread; q2 pair-fusion and pt). Packed epilogue stores.
// ============================================================================
template<int AMODE, int BPRE, int WR, int WC>
__global__ void __launch_bounds__(256, 2) tgemm2(
    const __nv_bfloat16* __restrict__ Ah, const __nv_bfloat16* __restrict__ Al, int lakp,
    const __nv_bfloat16* __restrict__ Bh, const __nv_bfloat16* __restrict__ Bl, int lbkp,
    const float* __restrict__ Bf, int ldbf,
    const float* __restrict__ bias_n, const float* __restrict__ rowt,
    float* __restrict__ Cf, __nv_bfloat16* __restrict__ Ch, __nv_bfloat16* __restrict__ Cl,
    int ldchl, int M, int Nn, int K, int relu, long zstride)
{
    constexpr int BM = WR*32, BN = WC*32;
    constexpr int ALOo = BM*80, BHIo = BM*160, BLOo = BM*160 + BN*80;
    constexpr int BUFSZ = (BM + BN) * 160;
    extern __shared__ char smem[];
    uint32_t sbase = smem_u32(smem);
    int tid = threadIdx.x, lane = tid & 31, wid = tid >> 5;
    int wm = wid % WR, wn = wid / WR;
    int m0 = blockIdx.y * BM, n0 = blockIdx.x * BN;

    int nk = (K + 31) >> 5;
    int chunk = (nk + gridDim.z - 1) / gridDim.z;
    int ks0 = blockIdx.z * chunk;
    int ks1 = min(nk, ks0 + chunk);
    float* Czf = Cf ? Cf + (size_t)blockIdx.z * zstride : nullptr;

    constexpr int NA = (AMODE == 1) ? (BM / 32) : 1;
    const char* asrc[NA];
    uint32_t adst[NA];
    if (AMODE == 1) {
        #pragma unroll
        for (int s = 0; s < NA; s++) {
            int g = tid + s * 256;
            int half = (g >= BM * 4);
            int g2 = g - half * BM * 4;
            int row = g2 >> 2, seg = g2 & 3;
            const __nv_bfloat16* base = half ? Al : Ah;
            asrc[s] = (const char*)(base + (size_t)(m0 + row) * lakp + seg * 8);
            adst[s] = half * ALOo + row * 80 + seg * 16;
        }
    }
    constexpr int NSEGA = BM / 64;
    int arow[NSEGA], asegc[NSEGA];
    const float *apf[NSEGA], *apf2[NSEGA];
    float4 sa0[NSEGA], sa1[NSEGA];
    const float4 f4z = make_float4(0.f, 0.f, 0.f, 0.f);
    if (AMODE == 2) {
        #pragma unroll
        for (int s = 0; s < NSEGA; s++) {
            int idx = tid + s * 256;
            arow[s] = idx >> 2; asegc[s] = idx & 3;
            int gm = m0 + arow[s];
            int b = gm / PP, p = gm - b * PP;
            apf[s]  = d_Aq + (size_t)(b * 32 + d_pi[p]) * Q1S;
            apf2[s] = d_Bq + (size_t)(b * 32 + d_pj[p]) * Q1S;
        }
    }
    constexpr int NB = (BPRE == 1) ? (BN / 32) : 1;
    const char* bsrc[NB];
    uint32_t bdst[NB];
    if (BPRE == 1) {
        #pragma unroll
        for (int s = 0; s < NB; s++) {
            int g = tid + s * 256;
            if (g < BN * 8) {
                int half = (g >= BN * 4);
                int g2 = g - half * BN * 4;
                int row = g2 >> 2, seg = g2 & 3;
                const __nv_bfloat16* base = half ? Bl : Bh;
                bsrc[s] = (const char*)(base + (size_t)(n0 + row) * lbkp + seg * 8);
                bdst[s] = BHIo + half * (BLOo - BHIo) + row * 80 + seg * 16;
            } else { bsrc[s] = nullptr; bdst[s] = 0; }
        }
    }
    bool bact = (tid < BN * 4);
    int brow = tid >> 2, bsegc = tid & 3;
    const float* bpf = (BPRE == 0) ? (Bf + (size_t)brow * ldbf) : nullptr;
    float4 sb0 = f4z, sb1 = f4z;

    auto cpa_pre = [&](int ik, uint32_t bufo) {
        if (AMODE == 1) {
            #pragma unroll
            for (int s = 0; s < NA; s++) cpa16(sbase + bufo + adst[s], asrc[s] + (size_t)ik * 64);
        }
        if (BPRE == 1) {
            #pragma unroll
            for (int s = 0; s < NB; s++)
                if (bsrc[s]) cpa16(sbase + bufo + bdst[s], bsrc[s] + (size_t)ik * 64);
        }
    };
    auto load_regs = [&](int ik) {
        int kg = ik * 32;
        if (AMODE == 2) {
            #pragma unroll
            for (int s = 0; s < NSEGA; s++) {
                int gk = kg + asegc[s] * 8;
                if (gk < K) {
                    float4 u = *(const float4*)(apf[s] + gk), v = *(const float4*)(apf2[s] + gk);
                    sa0[s] = make_float4(fmaxf(u.x+v.x,0.f), fmaxf(u.y+v.y,0.f),
                                         fmaxf(u.z+v.z,0.f), fmaxf(u.w+v.w,0.f));
                } else sa0[s] = f4z;
                if (gk + 4 < K) {
                    float4 u = *(const float4*)(apf[s] + gk + 4), v = *(const float4*)(apf2[s] + gk + 4);
                    sa1[s] = make_float4(fmaxf(u.x+v.x,0.f), fmaxf(u.y+v.y,0.f),
                                         fmaxf(u.z+v.z,0.f), fmaxf(u.w+v.w,0.f));
                } else sa1[s] = f4z;
            }
        }
        if (BPRE == 0 && bact) {
            int gk = kg + bsegc * 8;
            sb0 = (gk < K)     ? *(const float4*)(bpf + gk)     : f4z;
            sb1 = (gk + 4 < K) ? *(const float4*)(bpf + gk + 4) : f4z;
        }
    };
    auto conv_store = [&](char* buf) {
        if (AMODE == 2) {
            #pragma unroll
            for (int s = 0; s < NSEGA; s++) {
                uint4 H, L; conv8(sa0[s], sa1[s], H, L);
                *(uint4*)(buf + arow[s]*80 + asegc[s]*16) = H;
                *(uint4*)(buf + ALOo + arow[s]*80 + asegc[s]*16) = L;
            }
        }
        if (BPRE == 0 && bact) {
            uint4 H, L; conv8(sb0, sb1, H, L);
            *(uint4*)(buf + BHIo + brow*80 + bsegc*16) = H;
            *(uint4*)(buf + BLOo + brow*80 + bsegc*16) = L;
        }
    };

    uint32_t aoff[2], boff[4];
    #pragma unroll
    for (int mt = 0; mt < 2; mt++)
        aoff[mt] = (uint32_t)(((wm*32 + mt*16 + (lane & 15)) * 40 + ((lane >> 4) & 1) * 8) * 2);
    #pragma unroll
    for (int nt = 0; nt < 4; nt++)
        boff[nt] = (uint32_t)(((wn*32 + nt*8 + (lane & 7)) * 40 + ((lane >> 3) & 1) * 8) * 2);

    float acc[2][4][4];
    #pragma unroll
    for (int mt = 0; mt < 2; mt++)
        #pragma unroll
        for (int nt = 0; nt < 4; nt++)
            #pragma unroll
            for (int q = 0; q < 4; q++) acc[mt][nt][q] = 0.f;

    cpa_pre(ks0, 0); CPA_COMMIT();
    load_regs(ks0);
    conv_store(smem);
    for (int i = ks0; i < ks1; i++) {
        bool more = (i + 1 < ks1);
        if (more) { cpa_pre(i + 1, ((i + 1 - ks0) & 1) * BUFSZ); CPA_COMMIT(); load_regs(i + 1); }
        if (more) CPA_WAITN(1); else CPA_WAITN(0);
        __syncthreads();
        uint32_t tb = sbase + ((i - ks0) & 1) * BUFSZ;
        #pragma unroll
        for (int kh = 0; kh < 2; kh++) {
            uint32_t ah[2][4], al[2][4], bh[4][2], bl[4][2];
            #pragma unroll
            for (int mt = 0; mt < 2; mt++) {
                ldsm4(ah[mt], tb + aoff[mt] + kh*32);
                ldsm4(al[mt], tb + ALOo + aoff[mt] + kh*32);
            }
            #pragma unroll
            for (int nt = 0; nt < 4; nt++) {
                ldsm2(bh[nt], tb + BHIo + boff[nt] + kh*32);
                ldsm2(bl[nt], tb + BLOo + boff[nt] + kh*32);
            }
            #pragma unroll
            for (int mt = 0; mt < 2; mt++)
                #pragma unroll
                for (int nt = 0; nt < 4; nt++) {
                    mma16816(acc[mt][nt], ah[mt], bh[nt]);
                    mma16816(acc[mt][nt], ah[mt], bl[nt]);
                    mma16816(acc[mt][nt], al[mt], bh[nt]);
                }
        }
        if (more) conv_store(smem + ((i + 1 - ks0) & 1) * BUFSZ);
        __syncthreads();
    }

    #pragma unroll
    for (int mt = 0; mt < 2; mt++) {
        #pragma unroll
        for (int half = 0; half < 2; half++) {
            int gm = m0 + wm*32 + mt*16 + (lane >> 2) + half*8;
            if (gm >= M) continue;
            int bidx = gm / PP;
            #pragma unroll
            for (int nt = 0; nt < 4; nt++) {
                int gn = n0 + wn*32 + nt*8 + (lane & 3) * 2;
                float v0 = acc[mt][nt][half*2+0];
                float v1 = acc[mt][nt][half*2+1];
                bool ok0 = gn < Nn, ok1 = gn + 1 < Nn;
                if (bias_n) { if (ok0) v0 += bias_n[gn]; if (ok1) v1 += bias_n[gn+1]; }
                if (rowt)   { if (ok0) v0 += rowt[(size_t)gn*32 + bidx];
                              if (ok1) v1 += rowt[(size_t)(gn+1)*32 + bidx]; }
                if (relu)   { v0 = fmaxf(v0, 0.f); v1 = fmaxf(v1, 0.f); }
                if (Czf) {
                    if (ok0 && ok1) {
                        *(float2*)(Czf + (size_t)gm * Nn + gn) = make_float2(v0, v1);
                    } else {
                        if (ok0) Czf[(size_t)gm * Nn + gn] = v0;
                        if (ok1) Czf[(size_t)gm * Nn + gn + 1] = v1;
                    }
                } else if (gn < ldchl) {
                    float w0 = ok0 ? v0 : 0.f, w1 = ok1 ? v1 : 0.f;
                    unsigned h0, l0, h1, l1;
                    bsplit(w0, h0, l0); bsplit(w1, h1, l1);
                    *(unsigned*)(Ch + (size_t)gm * ldchl + gn) = h0 | (h1 << 16);
                    *(unsigned*)(Cl + (size_t)gm * ldchl + gn) = l0 | (l1 << 16);
                }
            }
        }
    }
}

// ============================================================================
// Persistent fused LSTM (144 CTAs, 32 steps).
// ============================================================================
__device__ __forceinline__ void gridbar(unsigned n) {
    __syncthreads();
    __threadfence();
    if (threadIdx.x == 0) {
        unsigned tk = atomicAdd(&g_bar, 1u);
        unsigned target = (tk / n + 1u) * n;
        while (atomicAdd(&g_bar, 0u) < target) { __nanosleep(64); }
    }
    __syncthreads();
}

__global__ void __launch_bounds__(256) k_lstm_all(
    const float* __restrict__ b_ih, const float* __restrict__ b_hh)
{
    constexpr int BM = 256, BN = 32;
    constexpr int ALOo = BM*80, BHIo = BM*160, BLOo = BM*160 + BN*80;
    constexpr int BUFSZ = (BM + BN) * 160;
    extern __shared__ char smem[];
    uint32_t sbase = smem_u32(smem);
    int tid = threadIdx.x, lane = tid & 31, wid = tid >> 5;
    int wm = wid;
    int bid = blockIdx.x;
    int z = bid % NZL, my = bid / NZL;
    int m0 = my * 256;
    const int nk = 47;
    int ks0 = z * 8, ks1 = min(nk, ks0 + 8);

    const char* asrc[8]; uint32_t adst[8];
    #pragma unroll
    for (int s = 0; s < 8; s++) {
        int g = tid + s * 256;
        int half = (g >= BM * 4);
        int g2 = g - half * BM * 4;
        int row = g2 >> 2, seg = g2 & 3;
        const __nv_bfloat16* base = half ? d_whh_l : d_whh_h;
        asrc[s] = (const char*)(base + (size_t)(m0 + row) * KP_H + seg * 8);
        adst[s] = half * ALOo + row * 80 + seg * 16;
    }
    bool bact = (tid < 128);
    int brow = tid >> 2, bsegc = tid & 3;
    const float4 f4z = make_float4(0.f,0.f,0.f,0.f);

    uint32_t aoff[2], boff[4];
    #pragma unroll
    for (int mt = 0; mt < 2; mt++)
        aoff[mt] = (uint32_t)(((wm*32 + mt*16 + (lane & 15)) * 40 + ((lane >> 4) & 1) * 8) * 2);
    #pragma unroll
    for (int nt = 0; nt < 4; nt++)
        boff[nt] = (uint32_t)(((nt*8 + (lane & 7)) * 40 + ((lane >> 3) & 1) * 8) * 2);

    float* gp = d_gpart6[z];

    for (int t = 0; t < 32; t++) {
        const float* hprev = d_h[t & 1];
        const float* bpf = hprev + (size_t)brow * HH;
        float4 sb0 = f4z, sb1 = f4z;

        auto cpa_pre = [&](int ik, uint32_t bufo) {
            #pragma unroll
            for (int s = 0; s < 8; s++) cpa16(sbase + bufo + adst[s], asrc[s] + (size_t)ik * 64);
        };
        auto load_b = [&](int ik) {
            if (!bact) return;
            int gk = ik * 32 + bsegc * 8;
            sb0 = (gk < HH)     ? __ldcg((const float4*)(bpf + gk))     : f4z;
            sb1 = (gk + 4 < HH) ? __ldcg((const float4*)(bpf + gk + 4)) : f4z;
        };
        auto store_b = [&](char* buf) {
            if (!bact) return;
            uint4 H, L; conv8(sb0, sb1, H, L);
            *(uint4*)(buf + BHIo + brow*80 + bsegc*16) = H;
            *(uint4*)(buf + BLOo + brow*80 + bsegc*16) = L;
        };

        float acc[2][4][4];
        #pragma unroll
        for (int mt = 0; mt < 2; mt++)
            #pragma unroll
            for (int nt = 0; nt < 4; nt++)
                #pragma unroll
                for (int q = 0; q < 4; q++) acc[mt][nt][q] = 0.f;

        cpa_pre(ks0, 0); CPA_COMMIT();
        load_b(ks0); store_b(smem);
        for (int i = ks0; i < ks1; i++) {
            bool more = (i + 1 < ks1);
            if (more) { cpa_pre(i + 1, ((i + 1 - ks0) & 1) * BUFSZ); CPA_COMMIT(); load_b(i + 1); }
            if (more) CPA_WAITN(1); else CPA_WAITN(0);
            __syncthreads();
            uint32_t tb = sbase + ((i - ks0) & 1) * BUFSZ;
            #pragma unroll
            for (int kh = 0; kh < 2; kh++) {
                uint32_t ah[2][4], al[2][4], bh[4][2], bl[4][2];
                #pragma unroll
                for (int mt = 0; mt < 2; mt++) {
                    ldsm4(ah[mt], tb + aoff[mt] + kh*32);
                    ldsm4(al[mt], tb + ALOo + aoff[mt] + kh*32);
                }
                #pragma unroll
                for (int nt = 0; nt < 4; nt++) {
                    ldsm2(bh[nt], tb + BHIo + boff[nt] + kh*32);
                    ldsm2(bl[nt], tb + BLOo + boff[nt] + kh*32);
                }
                #pragma unroll
                for (int mt = 0; mt < 2; mt++)
                    #pragma unroll
                    for (int nt = 0; nt < 4; nt++) {
                        mma16816(acc[mt][nt], ah[mt], bh[nt]);
                        mma16816(acc[mt][nt], ah[mt], bl[nt]);
                        mma16816(acc[mt][nt], al[mt], bh[nt]);
                    }
            }
            if (more) store_b(smem + ((i + 1 - ks0) & 1) * BUFSZ);
            __syncthreads();
        }

        #pragma unroll
        for (int mt = 0; mt < 2; mt++)
            #pragma unroll
            for (int half = 0; half < 2; half++) {
                int gm = m0 + wm*32 + mt*16 + (lane >> 2) + half*8;
                #pragma unroll
                for (int nt = 0; nt < 4; nt++) {
                    int gn = nt*8 + (lane & 3) * 2;
                    *(float2*)(gp + (size_t)gm * 32 + gn) =
                        make_float2(acc[mt][nt][half*2+0], acc[mt][nt][half*2+1]);
                }
            }

        gridbar(144);

        for (int e = bid * 256 + tid; e < BB * HH; e += 144 * 256) {
            int j = e >> 5, b = e & 31;
            float g[4];
            #pragma unroll
            for (int gg = 0; gg < 4; gg++) {
                int r = gg * HH + j;
                float v = d_xp[(size_t)r * MNB + t * 32 + b] + b_ih[r] + b_hh[r];
                #pragma unroll
                for (int zz = 0; zz < NZL; zz++) v += __ldcg(&d_gpart6[zz][(size_t)r * 32 + b]);
                g[gg] = v;
            }
            float ci = 1.f / (1.f + expf(-g[0]));
            float cf = 1.f / (1.f + expf(-g[1]));
            float cg = tanhf(g[2]);
            float co = 1.f / (1.f + expf(-g[3]));
            float cn = cf * d_cT[e] + ci * cg;
            d_cT[e] = cn;
            d_h[(t + 1) & 1][b * HH + j] = co * tanhf(cn);
        }

        gridbar(144);
    }
}

// ---------------- sort ----------------
__global__ void k_sort(const float* __restrict__ x) {
    int tid = blockIdx.x * blockDim.x + threadIdx.x;
    int b = tid >> 8, e = tid & 255;
    float v[32];
    #pragma unroll
    for (int t = 0; t < 32; t++) v[t] = x[(b * 32 + t) * EE + e];
    for (int a = 1; a < 32; a++) {
        float key = v[a];
        int c = a - 1;
        while (c >= 0 && v[c] > key) { v[c + 1] = v[c]; c--; }
        v[c + 1] = key;
    }
    #pragma unroll
    for (int t = 0; t < 32; t++) {
        unsigned hh, ll; bsplit(v[t], hh, ll);
        size_t idx = (size_t)(t * 32 + b) * KP_E + e;
        d_S_h[idx] = __ushort_as_bfloat16((unsigned short)hh);
        d_S_l[idx] = __ushort_as_bfloat16((unsigned short)ll);
    }
}

// ---------------- vectorized f32 -> hi/lo padded converter ----------------
__global__ void k_conv(const float* __restrict__ src, int ld, int Mr, int Kr,
                       __nv_bfloat16* __restrict__ h, __nv_bfloat16* __restrict__ l,
                       int Kp, long total)
{
    long idx8 = ((long)blockIdx.x * 256 + threadIdx.x) * 8;
    if (idx8 >= total) return;
    int r = (int)(idx8 / Kp), c = (int)(idx8 - (long)r * Kp);
    uint4 H, L;
    if (r < Mr && c + 7 < Kr) {
        const float* p = src + (size_t)r * ld + c;
        conv8(*(const float4*)p, *(const float4*)(p + 4), H, L);
    } else {
        float v[8];
        #pragma unroll
        for (int i = 0; i < 8; i++) {
            int cc = c + i;
            v[i] = (r < Mr && cc < Kr) ? src[(size_t)r * ld + cc] : 0.f;
        }
        conv8(make_float4(v[0],v[1],v[2],v[3]), make_float4(v[4],v[5],v[6],v[7]), H, L);
    }
    *(uint4*)(h + idx8) = H;
    *(uint4*)(l + idx8) = L;
}

// ---------------- init ----------------
__global__ void k_init(const float* __restrict__ q1_w, const float* __restrict__ q1_b) {
    int idx = blockIdx.x * blockDim.x + threadIdx.x;
    if (idx < PP) {
        int p = idx, i = 0, cnt = 31;
        while (p >= cnt) { p -= cnt; i++; cnt--; }
        d_pi[idx] = i; d_pj[idx] = i + 1 + p;
    } else if (idx < PP + Q1S) {
        int o = idx - PP;
        float s = q1_b[o];
        for (int d = 1; d < 2 * EE; d += 2) s += q1_w[o * (2 * EE) + d];
        d_q1beff[o] = s;
    } else {
        int zz = idx - (PP + Q1S);
        if (zz < BB * HH)           d_h[0][zz] = 0.f;
        else if (zz < 2 * BB * HH)  d_h[1][zz - BB * HH] = 0.f;
        else if (zz < 3 * BB * HH)  d_cT[zz - 2 * BB * HH] = 0.f;
    }
}

// ---------------- pt combine ----------------
__global__ void k_ptcomb(const float* __restrict__ e1_b) {
    int idx = blockIdx.x * blockDim.x + threadIdx.x;
    if (idx >= EV1S * BB) return;
    int n = idx >> 5;
    float v = e1_b[n];
    #pragma unroll
    for (int z = 0; z < 4; z++) v += d_pt4[z][idx];
    d_ptT[idx] = v;
}

// ---------------- tail: e3 + e4 ----------------
__global__ void k_tail(const float* __restrict__ e3w, const float* __restrict__ e3b,
                       const float* __restrict__ e4w, const float* __restrict__ e4b,
                       float* __restrict__ out)
{
    __shared__ float s2[64][101];
    __shared__ float sw[10][100];
    __shared__ float sb[10], s4[10];
    __shared__ float s4b;
    int m0 = blockIdx.x * 64;
    int tid = threadIdx.x;
    for (int l = 0; l < 100; l++) {
        int idx = tid + l * 64;
        s2[idx / 100][idx % 100] = d_e2buf[(size_t)m0 * EV2S + idx];
    }
    if (tid < 10) { sb[tid] = e3b[tid]; s4[tid] = e4w[tid]; }
    if (tid == 0) s4b = e4b[0];
    for (int l = tid; l < 1000; l += 64) sw[l / 100][l % 100] = e3w[l];
    __syncthreads();
    float acc = s4b;
    #pragma unroll
    for (int g = 0; g < 10; g++) {
        float a = sb[g];
        #pragma unroll 4
        for (int k = 0; k < 100; k++) a = fmaf(s2[tid][k], sw[g][k], a);
        acc = fmaf(fmaxf(a, 0.f), s4[g], acc);
    }
    out[m0 + tid] = fmaxf(acc, 0.f);
}

// ---------------- launch (R10 schedule + packed stores) ----------------
#define SM42 ((128+64)*160*2)
#define SM81 ((256+32)*160*2)
#define SM512 (40960*3)

extern "C" void kernel_launch(void* const* d_in, const int* in_sizes, int n_in,
                              void* d_out, int out_size)
{
    const float* x    = (const float*)d_in[0];
    const float* w_ih = (const float*)d_in[1];
    const float* w_hh = (const float*)d_in[2];
    const float* b_ih = (const float*)d_in[3];
    const float* b_hh = (const float*)d_in[4];
    const float* q1_w = (const float*)d_in[5];
    const float* q1_b = (const float*)d_in[6];
    const float* q2_w = (const float*)d_in[7];
    const float* q2_b = (const float*)d_in[8];
    const float* e1_w = (const float*)d_in[9];
    const float* e1_b = (const float*)d_in[10];
    const float* e2_w = (const float*)d_in[11];
    const float* e2_b = (const float*)d_in[12];
    const float* e3_w = (const float*)d_in[13];
    const float* e3_b = (const float*)d_in[14];
    const float* e4_w = (const float*)d_in[15];
    const float* e4_b = (const float*)d_in[16];
    float* out = (float*)d_out;

    static cudaStream_t s2s = nullptr;
    static cudaEvent_t evFork = nullptr, evJoin = nullptr;
    static bool inited = false;
    if (!inited) {
        cudaStreamCreateWithFlags(&s2s, cudaStreamNonBlocking);
        cudaEventCreateWithFlags(&evFork, cudaEventDisableTiming);
        cudaEventCreateWithFlags(&evJoin, cudaEventDisableTiming);
        cudaFuncSetAttribute((const void*)tgemm512,        cudaFuncAttributeMaxDynamicSharedMemorySize, SM512);
        cudaFuncSetAttribute((const void*)tgemm2<2,1,4,2>, cudaFuncAttributeMaxDynamicSharedMemorySize, SM42);
        cudaFuncSetAttribute((const void*)tgemm2<1,0,8,1>, cudaFuncAttributeMaxDynamicSharedMemorySize, SM81);
        cudaFuncSetAttribute((const void*)k_lstm_all,      cudaFuncAttributeMaxDynamicSharedMemorySize, SM81);
        inited = true;
    }

    float *pXp, *pH0, *pPt4, *pPt, *pQb, *pAq, *pBq, *pE2;
    __nv_bfloat16 *pWih_h,*pWih_l,*pS_h,*pS_l,*pX_h,*pX_l,*pQ1A_h,*pQ1A_l,*pQ1B_h,*pQ1B_l;
    __nv_bfloat16 *pQ2w_h,*pQ2w_l,*pE1H_h,*pE1H_l,*pE1Q_h,*pE1Q_l,*pE2w_h,*pE2w_l;
    __nv_bfloat16 *pWhh_h,*pWhh_l,*pQ2o_h,*pQ2o_l,*pE1o_h,*pE1o_l;
    cudaGetSymbolAddress((void**)&pXp,  d_xp);
    cudaGetSymbolAddress((void**)&pH0,  d_h);
    cudaGetSymbolAddress((void**)&pPt4, d_pt4);
    cudaGetSymbolAddress((void**)&pPt,  d_ptT);
    cudaGetSymbolAddress((void**)&pQb,  d_q1beff);
    cudaGetSymbolAddress((void**)&pAq,  d_Aq);
    cudaGetSymbolAddress((void**)&pBq,  d_Bq);
    cudaGetSymbolAddress((void**)&pE2,  d_e2buf);
    cudaGetSymbolAddress((void**)&pWih_h, d_wih_h); cudaGetSymbolAddress((void**)&pWih_l, d_wih_l);
    cudaGetSymbolAddress((void**)&pS_h,  d_S_h);    cudaGetSymbolAddress((void**)&pS_l,  d_S_l);
    cudaGetSymbolAddress((void**)&pX_h,  d_x_h);    cudaGetSymbolAddress((void**)&pX_l,  d_x_l);
    cudaGetSymbolAddress((void**)&pQ1A_h, d_q1wA_h); cudaGetSymbolAddress((void**)&pQ1A_l, d_q1wA_l);
    cudaGetSymbolAddress((void**)&pQ1B_h, d_q1wB_h); cudaGetSymbolAddress((void**)&pQ1B_l, d_q1wB_l);
    cudaGetSymbolAddress((void**)&pQ2w_h, d_q2w_h);  cudaGetSymbolAddress((void**)&pQ2w_l, d_q2w_l);
    cudaGetSymbolAddress((void**)&pE1H_h, d_e1wH_h); cudaGetSymbolAddress((void**)&pE1H_l, d_e1wH_l);
    cudaGetSymbolAddress((void**)&pE1Q_h, d_e1wQ_h); cudaGetSymbolAddress((void**)&pE1Q_l, d_e1wQ_l);
    cudaGetSymbolAddress((void**)&pE2w_h, d_e2w_h);  cudaGetSymbolAddress((void**)&pE2w_l, d_e2w_l);
    cudaGetSymbolAddress((void**)&pWhh_h, d_whh_h);  cudaGetSymbolAddress((void**)&pWhh_l, d_whh_l);
    cudaGetSymbolAddress((void**)&pQ2o_h, d_q2o_h);  cudaGetSymbolAddress((void**)&pQ2o_l, d_q2o_l);
    cudaGetSymbolAddress((void**)&pE1o_h, d_e1o_h);  cudaGetSymbolAddress((void**)&pE1o_l, d_e1o_l);

    // ---- main: sort + init ----
    k_sort<<<32, 256>>>(x);
    k_init<<<(PP + Q1S + 3 * BB * HH + 255) / 256, 256>>>(q1_w, q1_b);

    cudaEventRecord(evFork, 0);
    cudaStreamWaitEvent(s2s, evFork, 0);

    // ---- side stream: pair-query chain ----
    k_conv<<<(int)(((long)MNB*KP_E/8 + 255)/256), 256, 0, s2s>>>(x, EE, MNB, EE, pX_h, pX_l, KP_E, (long)MNB*KP_E);
    k_conv<<<(int)(((long)640*KP_E/8 + 255)/256), 256, 0, s2s>>>(q1_w, 2*EE, Q1S, EE, pQ1A_h, pQ1A_l, KP_E, (long)640*KP_E);
    k_conv<<<(int)(((long)640*KP_E/8 + 255)/256), 256, 0, s2s>>>(q1_w+EE, 2*EE, Q1S, EE, pQ1B_h, pQ1B_l, KP_E, (long)640*KP_E);
    k_conv<<<(int)(((long)320*KP_Q1/8 + 255)/256), 256, 0, s2s>>>(q2_w, Q1S, QS, Q1S, pQ2w_h, pQ2w_l, KP_Q1, (long)320*KP_Q1);
    tgemm512<<<dim3(5, 8), 512, SM512, s2s>>>(
        pX_h, pX_l, KP_E, pQ1A_h, pQ1A_l, KP_E,
        pQb, nullptr, pAq, nullptr, nullptr, 0, MNB, Q1S, KP_E, 0);
    tgemm512<<<dim3(5, 8), 512, SM512, s2s>>>(
        pX_h, pX_l, KP_E, pQ1B_h, pQ1B_l, KP_E,
        nullptr, nullptr, pBq, nullptr, nullptr, 0, MNB, Q1S, KP_E, 0);
    tgemm2<2,1,4,2><<<dim3(5, 124, 1), 256, SM42, s2s>>>(
        nullptr, nullptr, 0, pQ2w_h, pQ2w_l, KP_Q1, nullptr, 0,
        q2_b, nullptr, nullptr, pQ2o_h, pQ2o_l, KP_Q, MPAIR, QS, Q1S, 1, 0);
    cudaEventRecord(evJoin, s2s);

    // ---- main: LSTM-side + evaluator-weight convs, then xp + LSTM ----
    k_conv<<<(int)(((long)6016*KP_E/8 + 255)/256), 256>>>(w_ih, EE, G4, EE, pWih_h, pWih_l, KP_E, (long)6016*KP_E);
    k_conv<<<(int)(((long)G4P*KP_H/8 + 255)/256), 256>>>(w_hh, HH, G4, HH, pWhh_h, pWhh_l, KP_H, (long)G4P*KP_H);
    k_conv<<<(int)(((long)1024*KP_H/8 + 255)/256), 256>>>(e1_w, HH+QS, EV1S, HH, pE1H_h, pE1H_l, KP_H, (long)1024*KP_H);
    k_conv<<<(int)(((long)1024*KP_Q/8 + 255)/256), 256>>>(e1_w+HH, HH+QS, EV1S, QS, pE1Q_h, pE1Q_l, KP_Q, (long)1024*KP_Q);
    k_conv<<<(int)(((long)128*KP_E2/8 + 255)/256), 256>>>(e2_w, EV1S, EV2S, EV1S, pE2w_h, pE2w_l, KP_E2, (long)128*KP_E2);

    tgemm512<<<dim3(8, 47), 512, SM512>>>(
        pWih_h, pWih_l, KP_E, pS_h, pS_l, KP_E,
        nullptr, nullptr, pXp, nullptr, nullptr, 0, G4, MNB, KP_E, 0);

    k_lstm_all<<<144, 256, SM81>>>(b_ih, b_hh);

    // pt partials + combine
    tgemm2<1,0,8,1><<<dim3(1, 4, 4), 256, SM81>>>(
        pE1H_h, pE1H_l, KP_H, nullptr, nullptr, 0, pH0, HH,
        nullptr, nullptr, pPt4, nullptr, nullptr, 0, EV1S, BB, HH, 0, (long)PTP * BB);
    k_ptcomb<<<(EV1S * BB + 255) / 256, 256>>>(e1_b);

    // join side chain, then evaluator chain
    cudaStreamWaitEvent(0, evJoin, 0);

    tgemm512<<<dim3(8, 124), 512, SM512>>>(
        pQ2o_h, pQ2o_l, KP_Q, pE1Q_h, pE1Q_l, KP_Q,
        nullptr, pPt, nullptr, pE1o_h, pE1o_l, KP_E2, MPAIR, EV1S, KP_Q, 1);

    tgemm512<<<dim3(1, 124), 512, SM512>>>(
        pE1o_h, pE1o_l, KP_E2, pE2w_h, pE2w_l, KP_E2,
        e2_b, nullptr, pE2, nullptr, nullptr, 0, MPAIR, EV2S, KP_E2, 1);

    k_tail<<<MPAIR / 64, 64>>>(e3_w, e3_b, e4_w, e4_b, out);
}

// round 16
// speedup vs baseline: 1.2945x; 1.0811x over previous
#include <cuda_runtime.h>
#include <cuda_bf16.h>
#include <math.h>
#include <stdint.h>

// ---------------- constants ----------------
#define BB 32
#define EE 256
#define HH 1500
#define G4 6000
#define PP 496
#define Q1S 600
#define QS 300
#define EV1S 1000
#define EV2S 100
#define MPAIR (BB*PP)   // 15872
#define MNB 1024
#define G4P 6144
#define PTP 1024
#define NZL 6
#define KP_E 256
#define KP_Q1 608
#define KP_Q 320
#define KP_E2 1024
#define KP_H 1536

// ---------------- f32 scratch ----------------
__device__ float d_xp[(size_t)G4*MNB];
__device__ float d_h[2][BB*HH];
__device__ float d_cT[BB*HH];
__device__ float d_gpart6[NZL][G4P*BB];
__device__ float d_pt4[4][PTP*BB];
__device__ float d_ptT[EV1S*BB];
__device__ float d_q1beff[Q1S];
__device__ float d_bsum[G4];
__device__ int   d_pi[PP], d_pj[PP];
__device__ float d_Aq[MNB*Q1S];
__device__ float d_Bq[MNB*Q1S];
__device__ float d_e2buf[MPAIR*EV2S];
__device__ unsigned g_bar;

// ---------------- bf16 hi/lo preconverted (zero-padded) ----------------
__device__ __nv_bfloat16 d_wih_h[6016*KP_E],  d_wih_l[6016*KP_E];
__device__ __nv_bfloat16 d_S_h[MNB*KP_E],     d_S_l[MNB*KP_E];
__device__ __nv_bfloat16 d_x_h[MNB*KP_E],     d_x_l[MNB*KP_E];
__device__ __nv_bfloat16 d_q1wA_h[640*KP_E],  d_q1wA_l[640*KP_E];
__device__ __nv_bfloat16 d_q1wB_h[640*KP_E],  d_q1wB_l[640*KP_E];
__device__ __nv_bfloat16 d_q2w_h[320*KP_Q1],  d_q2w_l[320*KP_Q1];
__device__ __nv_bfloat16 d_e1wH_h[1024*KP_H], d_e1wH_l[1024*KP_H];
__device__ __nv_bfloat16 d_e1wQ_h[1024*KP_Q], d_e1wQ_l[1024*KP_Q];
__device__ __nv_bfloat16 d_e2w_h[128*KP_E2],  d_e2w_l[128*KP_E2];
__device__ __nv_bfloat16 d_whh_h[(size_t)G4P*KP_H], d_whh_l[(size_t)G4P*KP_H];
__device__ __nv_bfloat16 d_q2o_h[(size_t)MPAIR*KP_Q], d_q2o_l[(size_t)MPAIR*KP_Q];
__device__ __nv_bfloat16 d_e1o_h[(size_t)MPAIR*KP_E2], d_e1o_l[(size_t)MPAIR*KP_E2];

// ---------------- helpers ----------------
__device__ __forceinline__ uint32_t smem_u32(const void* p) {
    uint32_t a;
    asm("{ .reg .u64 t; cvta.to.shared.u64 t, %1; cvt.u32.u64 %0, t; }" : "=r"(a) : "l"(p));
    return a;
}
__device__ __forceinline__ void ldsm4(uint32_t* r, uint32_t addr) {
    asm volatile("ldmatrix.sync.aligned.m8n8.x4.shared.b16 {%0,%1,%2,%3}, [%4];"
        : "=r"(r[0]), "=r"(r[1]), "=r"(r[2]), "=r"(r[3]) : "r"(addr));
}
__device__ __forceinline__ void ldsm2(uint32_t* r, uint32_t addr) {
    asm volatile("ldmatrix.sync.aligned.m8n8.x2.shared.b16 {%0,%1}, [%2];"
        : "=r"(r[0]), "=r"(r[1]) : "r"(addr));
}
__device__ __forceinline__ void mma16816(float* c, const uint32_t* a, const uint32_t* b) {
    asm volatile("mma.sync.aligned.m16n8k16.row.col.f32.bf16.bf16.f32 "
        "{%0,%1,%2,%3}, {%4,%5,%6,%7}, {%8,%9}, {%0,%1,%2,%3};"
        : "+f"(c[0]), "+f"(c[1]), "+f"(c[2]), "+f"(c[3])
        : "r"(a[0]), "r"(a[1]), "r"(a[2]), "r"(a[3]), "r"(b[0]), "r"(b[1]));
}
__device__ __forceinline__ void cpa16(uint32_t d, const void* s) {
    asm volatile("cp.async.cg.shared.global [%0], [%1], 16;" :: "r"(d), "l"(s));
}
#define CPA_COMMIT() asm volatile("cp.async.commit_group;" ::: "memory")
#define CPA_WAITN(n) asm volatile("cp.async.wait_group %0;" :: "n"(n) : "memory")

__device__ __forceinline__ void bsplit(float v, unsigned& h, unsigned& l) {
    __nv_bfloat16 bh = __float2bfloat16_rn(v);
    float r = v - __bfloat162float(bh);
    __nv_bfloat16 bl = __float2bfloat16_rn(r);
    h = (unsigned)__bfloat16_as_ushort(bh);
    l = (unsigned)__bfloat16_as_ushort(bl);
}
__device__ __forceinline__ void conv8(float4 a, float4 b, uint4& H, uint4& L) {
    unsigned h0,h1,h2,h3,h4,h5,h6,h7, l0,l1,l2,l3,l4,l5,l6,l7;
    bsplit(a.x,h0,l0); bsplit(a.y,h1,l1); bsplit(a.z,h2,l2); bsplit(a.w,h3,l3);
    bsplit(b.x,h4,l4); bsplit(b.y,h5,l5); bsplit(b.z,h6,l6); bsplit(b.w,h7,l7);
    H.x = h0 | (h1<<16); H.y = h2 | (h3<<16); H.z = h4 | (h5<<16); H.w = h6 | (h7<<16);
    L.x = l0 | (l1<<16); L.y = l2 | (l3<<16); L.z = l4 | (l5<<16); L.w = l6 | (l7<<16);
}
// fast, overflow-safe gate math (error ~1e-6)
__device__ __forceinline__ float fsigmoid(float x) {
    return __fdividef(1.f, 1.f + __expf(-x));
}
__device__ __forceinline__ float ftanh(float x) {
    float e = __expf(fminf(2.f * fabsf(x), 80.f));
    float t = 1.f - 2.f * __fdividef(1.f, e + 1.f);
    return copysignf(t, x);
}

// ============================================================================
// tgemm512: 512 threads, BM=BN=128, 3-stage cp.async. Packed epilogue stores.
// ============================================================================
__global__ void __launch_bounds__(512) tgemm512(
    const __nv_bfloat16* __restrict__ Ah, const __nv_bfloat16* __restrict__ Al, int lakp,
    const __nv_bfloat16* __restrict__ Bh, const __nv_bfloat16* __restrict__ Bl, int lbkp,
    const float* __restrict__ bias_n, const float* __restrict__ rowt,
    float* __restrict__ Cf, __nv_bfloat16* __restrict__ Ch, __nv_bfloat16* __restrict__ Cl,
    int ldchl, int M, int Nn, int Kp, int relu)
{
    constexpr int ALOo = 10240, BHIo = 20480, BLOo = 30720;
    constexpr int STG = 40960;
    extern __shared__ char smem[];
    uint32_t sbase = smem_u32(smem);
    int tid = threadIdx.x, lane = tid & 31, wid = tid >> 5;
    int wm = wid & 3, wn = wid >> 2;
    int m0 = blockIdx.y * 128, n0 = blockIdx.x * 128;

    const char* src[4]; uint32_t dst[4];
    #pragma unroll
    for (int s = 0; s < 4; s++) {
        int g = tid + s * 512;
        int isB = (g >= 1024);
        int g1 = g - isB * 1024;
        int half = (g1 >= 512);
        int g2 = g1 - half * 512;
        int row = g2 >> 2, seg = g2 & 3;
        const __nv_bfloat16* base = isB ? (half ? Bl : Bh) : (half ? Al : Ah);
        int ld = isB ? lbkp : lakp;
        int r0 = isB ? n0 : m0;
        src[s] = (const char*)(base + (size_t)(r0 + row) * ld + seg * 8);
        dst[s] = (uint32_t)(isB * BHIo + half * ALOo + row * 80 + seg * 16);
    }
    auto prefetch = [&](int ik, int buf) {
        uint32_t bo = (uint32_t)(buf * STG);
        #pragma unroll
        for (int s = 0; s < 4; s++) cpa16(sbase + bo + dst[s], src[s] + (size_t)ik * 64);
    };

    uint32_t aoff[2], boff[4];
    #pragma unroll
    for (int mt = 0; mt < 2; mt++)
        aoff[mt] = (uint32_t)(((wm*32 + mt*16 + (lane & 15)) * 40 + ((lane >> 4) & 1) * 8) * 2);
    #pragma unroll
    for (int nt = 0; nt < 4; nt++)
        boff[nt] = (uint32_t)(((wn*32 + nt*8 + (lane & 7)) * 40 + ((lane >> 3) & 1) * 8) * 2);

    float acc[2][4][4];
    #pragma unroll
    for (int mt = 0; mt < 2; mt++)
        #pragma unroll
        for (int nt = 0; nt < 4; nt++)
            #pragma unroll
            for (int q = 0; q < 4; q++) acc[mt][nt][q] = 0.f;

    int nk = Kp >> 5;
    prefetch(0, 0); CPA_COMMIT();
    if (nk > 1) prefetch(1, 1);
    CPA_COMMIT();

    for (int i = 0; i < nk; i++) {
        if (i + 1 < nk) CPA_WAITN(1); else CPA_WAITN(0);
        __syncthreads();
        if (i + 2 < nk) prefetch(i + 2, (i + 2) % 3);
        CPA_COMMIT();
        uint32_t tb = sbase + (uint32_t)((i % 3) * STG);
        #pragma unroll
        for (int kh = 0; kh < 2; kh++) {
            uint32_t ah[2][4], al[2][4], bh[4][2], bl[4][2];
            #pragma unroll
            for (int mt = 0; mt < 2; mt++) {
                ldsm4(ah[mt], tb + aoff[mt] + kh*32);
                ldsm4(al[mt], tb + ALOo + aoff[mt] + kh*32);
            }
            #pragma unroll
            for (int nt = 0; nt < 4; nt++) {
                ldsm2(bh[nt], tb + BHIo + boff[nt] + kh*32);
                ldsm2(bl[nt], tb + BLOo + boff[nt] + kh*32);
            }
            #pragma unroll
            for (int mt = 0; mt < 2; mt++)
                #pragma unroll
                for (int nt = 0; nt < 4; nt++) {
                    mma16816(acc[mt][nt], ah[mt], bh[nt]);
                    mma16816(acc[mt][nt], ah[mt], bl[nt]);
                    mma16816(acc[mt][nt], al[mt], bh[nt]);
                }
        }
        __syncthreads();
    }

    #pragma unroll
    for (int mt = 0; mt < 2; mt++) {
        #pragma unroll
        for (int half = 0; half < 2; half++) {
            int gm = m0 + wm*32 + mt*16 + (lane >> 2) + half*8;
            if (gm >= M) continue;
            int bidx = gm / PP;
            #pragma unroll
            for (int nt = 0; nt < 4; nt++) {
                int gn = n0 + wn*32 + nt*8 + (lane & 3) * 2;
                float v0 = acc[mt][nt][half*2+0];
                float v1 = acc[mt][nt][half*2+1];
                bool ok0 = gn < Nn, ok1 = gn + 1 < Nn;
                if (bias_n) { if (ok0) v0 += bias_n[gn]; if (ok1) v1 += bias_n[gn+1]; }
                if (rowt)   { if (ok0) v0 += rowt[(size_t)gn*32 + bidx];
                              if (ok1) v1 += rowt[(size_t)(gn+1)*32 + bidx]; }
                if (relu)   { v0 = fmaxf(v0, 0.f); v1 = fmaxf(v1, 0.f); }
                if (Cf) {
                    if (ok0 && ok1) {
                        *(float2*)(Cf + (size_t)gm * Nn + gn) = make_float2(v0, v1);
                    } else {
                        if (ok0) Cf[(size_t)gm * Nn + gn] = v0;
                        if (ok1) Cf[(size_t)gm * Nn + gn + 1] = v1;
                    }
                } else if (gn < ldchl) {
                    float w0 = ok0 ? v0 : 0.f, w1 = ok1 ? v1 : 0.f;
                    unsigned h0, l0, h1, l1;
                    bsplit(w0, h0, l0); bsplit(w1, h1, l1);
                    *(unsigned*)(Ch + (size_t)gm * ldchl + gn) = h0 | (h1 << 16);
                    *(unsigned*)(Cl + (size_t)gm * ldchl + gn) = l0 | (l1 << 16);
                }
            }
        }
    }
}

// ============================================================================
// tgemm2 (256-thread; q2 pair-fusion and pt). Packed epilogue stores.
// ============================================================================
template<int AMODE, int BPRE, int WR, int WC>
__global__ void __launch_bounds__(256, 2) tgemm2(
    const __nv_bfloat16* __restrict__ Ah, const __nv_bfloat16* __restrict__ Al, int lakp,
    const __nv_bfloat16* __restrict__ Bh, const __nv_bfloat16* __restrict__ Bl, int lbkp,
    const float* __restrict__ Bf, int ldbf,
    const float* __restrict__ bias_n, const float* __restrict__ rowt,
    float* __restrict__ Cf, __nv_bfloat16* __restrict__ Ch, __nv_bfloat16* __restrict__ Cl,
    int ldchl, int M, int Nn, int K, int relu, long zstride)
{
    constexpr int BM = WR*32, BN = WC*32;
    constexpr int ALOo = BM*80, BHIo = BM*160, BLOo = BM*160 + BN*80;
    constexpr int BUFSZ = (BM + BN) * 160;
    extern __shared__ char smem[];
    uint32_t sbase = smem_u32(smem);
    int tid = threadIdx.x, lane = tid & 31, wid = tid >> 5;
    int wm = wid % WR, wn = wid / WR;
    int m0 = blockIdx.y * BM, n0 = blockIdx.x * BN;

    int nk = (K + 31) >> 5;
    int chunk = (nk + gridDim.z - 1) / gridDim.z;
    int ks0 = blockIdx.z * chunk;
    int ks1 = min(nk, ks0 + chunk);
    float* Czf = Cf ? Cf + (size_t)blockIdx.z * zstride : nullptr;

    constexpr int NA = (AMODE == 1) ? (BM / 32) : 1;
    const char* asrc[NA];
    uint32_t adst[NA];
    if (AMODE == 1) {
        #pragma unroll
        for (int s = 0; s < NA; s++) {
            int g = tid + s * 256;
            int half = (g >= BM * 4);
            int g2 = g - half * BM * 4;
            int row = g2 >> 2, seg = g2 & 3;
            const __nv_bfloat16* base = half ? Al : Ah;
            asrc[s] = (const char*)(base + (size_t)(m0 + row) * lakp + seg * 8);
            adst[s] = half * ALOo + row * 80 + seg * 16;
        }
    }
    constexpr int NSEGA = BM / 64;
    int arow[NSEGA], asegc[NSEGA];
    const float *apf[NSEGA], *apf2[NSEGA];
    float4 sa0[NSEGA], sa1[NSEGA];
    const float4 f4z = make_float4(0.f, 0.f, 0.f, 0.f);
    if (AMODE == 2) {
        #pragma unroll
        for (int s = 0; s < NSEGA; s++) {
            int idx = tid + s * 256;
            arow[s] = idx >> 2; asegc[s] = idx & 3;
            int gm = m0 + arow[s];
            int b = gm / PP, p = gm - b * PP;
            apf[s]  = d_Aq + (size_t)(b * 32 + d_pi[p]) * Q1S;
            apf2[s] = d_Bq + (size_t)(b * 32 + d_pj[p]) * Q1S;
        }
    }
    constexpr int NB = (BPRE == 1) ? (BN / 32) : 1;
    const char* bsrc[NB];
    uint32_t bdst[NB];
    if (BPRE == 1) {
        #pragma unroll
        for (int s = 0; s < NB; s++) {
            int g = tid + s * 256;
            if (g < BN * 8) {
                int half = (g >= BN * 4);
                int g2 = g - half * BN * 4;
                int row = g2 >> 2, seg = g2 & 3;
                const __nv_bfloat16* base = half ? Bl : Bh;
                bsrc[s] = (const char*)(base + (size_t)(n0 + row) * lbkp + seg * 8);
                bdst[s] = BHIo + half * (BLOo - BHIo) + row * 80 + seg * 16;
            } else { bsrc[s] = nullptr; bdst[s] = 0; }
        }
    }
    bool bact = (tid < BN * 4);
    int brow = tid >> 2, bsegc = tid & 3;
    const float* bpf = (BPRE == 0) ? (Bf + (size_t)brow * ldbf) : nullptr;
    float4 sb0 = f4z, sb1 = f4z;

    auto cpa_pre = [&](int ik, uint32_t bufo) {
        if (AMODE == 1) {
            #pragma unroll
            for (int s = 0; s < NA; s++) cpa16(sbase + bufo + adst[s], asrc[s] + (size_t)ik * 64);
        }
        if (BPRE == 1) {
            #pragma unroll
            for (int s = 0; s < NB; s++)
                if (bsrc[s]) cpa16(sbase + bufo + bdst[s], bsrc[s] + (size_t)ik * 64);
        }
    };
    auto load_regs = [&](int ik) {
        int kg = ik * 32;
        if (AMODE == 2) {
            #pragma unroll
            for (int s = 0; s < NSEGA; s++) {
                int gk = kg + asegc[s] * 8;
                if (gk < K) {
                    float4 u = *(const float4*)(apf[s] + gk), v = *(const float4*)(apf2[s] + gk);
                    sa0[s] = make_float4(fmaxf(u.x+v.x,0.f), fmaxf(u.y+v.y,0.f),
                                         fmaxf(u.z+v.z,0.f), fmaxf(u.w+v.w,0.f));
                } else sa0[s] = f4z;
                if (gk + 4 < K) {
                    float4 u = *(const float4*)(apf[s] + gk + 4), v = *(const float4*)(apf2[s] + gk + 4);
                    sa1[s] = make_float4(fmaxf(u.x+v.x,0.f), fmaxf(u.y+v.y,0.f),
                                         fmaxf(u.z+v.z,0.f), fmaxf(u.w+v.w,0.f));
                } else sa1[s] = f4z;
            }
        }
        if (BPRE == 0 && bact) {
            int gk = kg + bsegc * 8;
            sb0 = (gk < K)     ? *(const float4*)(bpf + gk)     : f4z;
            sb1 = (gk + 4 < K) ? *(const float4*)(bpf + gk + 4) : f4z;
        }
    };
    auto conv_store = [&](char* buf) {
        if (AMODE == 2) {
            #pragma unroll
            for (int s = 0; s < NSEGA; s++) {
                uint4 H, L; conv8(sa0[s], sa1[s], H, L);
                *(uint4*)(buf + arow[s]*80 + asegc[s]*16) = H;
                *(uint4*)(buf + ALOo + arow[s]*80 + asegc[s]*16) = L;
            }
        }
        if (BPRE == 0 && bact) {
            uint4 H, L; conv8(sb0, sb1, H, L);
            *(uint4*)(buf + BHIo + brow*80 + bsegc*16) = H;
            *(uint4*)(buf + BLOo + brow*80 + bsegc*16) = L;
        }
    };

    uint32_t aoff[2], boff[4];
    #pragma unroll
    for (int mt = 0; mt < 2; mt++)
        aoff[mt] = (uint32_t)(((wm*32 + mt*16 + (lane & 15)) * 40 + ((lane >> 4) & 1) * 8) * 2);
    #pragma unroll
    for (int nt = 0; nt < 4; nt++)
        boff[nt] = (uint32_t)(((wn*32 + nt*8 + (lane & 7)) * 40 + ((lane >> 3) & 1) * 8) * 2);

    float acc[2][4][4];
    #pragma unroll
    for (int mt = 0; mt < 2; mt++)
        #pragma unroll
        for (int nt = 0; nt < 4; nt++)
            #pragma unroll
            for (int q = 0; q < 4; q++) acc[mt][nt][q] = 0.f;

    cpa_pre(ks0, 0); CPA_COMMIT();
    load_regs(ks0);
    conv_store(smem);
    for (int i = ks0; i < ks1; i++) {
        bool more = (i + 1 < ks1);
        if (more) { cpa_pre(i + 1, ((i + 1 - ks0) & 1) * BUFSZ); CPA_COMMIT(); load_regs(i + 1); }
        if (more) CPA_WAITN(1); else CPA_WAITN(0);
        __syncthreads();
        uint32_t tb = sbase + ((i - ks0) & 1) * BUFSZ;
        #pragma unroll
        for (int kh = 0; kh < 2; kh++) {
            uint32_t ah[2][4], al[2][4], bh[4][2], bl[4][2];
            #pragma unroll
            for (int mt = 0; mt < 2; mt++) {
                ldsm4(ah[mt], tb + aoff[mt] + kh*32);
                ldsm4(al[mt], tb + ALOo + aoff[mt] + kh*32);
            }
            #pragma unroll
            for (int nt = 0; nt < 4; nt++) {
                ldsm2(bh[nt], tb + BHIo + boff[nt] + kh*32);
                ldsm2(bl[nt], tb + BLOo + boff[nt] + kh*32);
            }
            #pragma unroll
            for (int mt = 0; mt < 2; mt++)
                #pragma unroll
                for (int nt = 0; nt < 4; nt++) {
                    mma16816(acc[mt][nt], ah[mt], bh[nt]);
                    mma16816(acc[mt][nt], ah[mt], bl[nt]);
                    mma16816(acc[mt][nt], al[mt], bh[nt]);
                }
        }
        if (more) conv_store(smem + ((i + 1 - ks0) & 1) * BUFSZ);
        __syncthreads();
    }

    #pragma unroll
    for (int mt = 0; mt < 2; mt++) {
        #pragma unroll
        for (int half = 0; half < 2; half++) {
            int gm = m0 + wm*32 + mt*16 + (lane >> 2) + half*8;
            if (gm >= M) continue;
            int bidx = gm / PP;
            #pragma unroll
            for (int nt = 0; nt < 4; nt++) {
                int gn = n0 + wn*32 + nt*8 + (lane & 3) * 2;
                float v0 = acc[mt][nt][half*2+0];
                float v1 = acc[mt][nt][half*2+1];
                bool ok0 = gn < Nn, ok1 = gn + 1 < Nn;
                if (bias_n) { if (ok0) v0 += bias_n[gn]; if (ok1) v1 += bias_n[gn+1]; }
                if (rowt)   { if (ok0) v0 += rowt[(size_t)gn*32 + bidx];
                              if (ok1) v1 += rowt[(size_t)(gn+1)*32 + bidx]; }
                if (relu)   { v0 = fmaxf(v0, 0.f); v1 = fmaxf(v1, 0.f); }
                if (Czf) {
                    if (ok0 && ok1) {
                        *(float2*)(Czf + (size_t)gm * Nn + gn) = make_float2(v0, v1);
                    } else {
                        if (ok0) Czf[(size_t)gm * Nn + gn] = v0;
                        if (ok1) Czf[(size_t)gm * Nn + gn + 1] = v1;
                    }
                } else if (gn < ldchl) {
                    float w0 = ok0 ? v0 : 0.f, w1 = ok1 ? v1 : 0.f;
                    unsigned h0, l0, h1, l1;
                    bsplit(w0, h0, l0); bsplit(w1, h1, l1);
                    *(unsigned*)(Ch + (size_t)gm * ldchl + gn) = h0 | (h1 << 16);
                    *(unsigned*)(Cl + (size_t)gm * ldchl + gn) = l0 | (l1 << 16);
                }
            }
        }
    }
}

// ============================================================================
// Persistent fused LSTM (144 CTAs, 32 steps). Fast gate math + float2 combine.
// ============================================================================
__device__ __forceinline__ void gridbar(unsigned n) {
    __syncthreads();
    __threadfence();
    if (threadIdx.x == 0) {
        unsigned tk = atomicAdd(&g_bar, 1u);
        unsigned target = (tk / n + 1u) * n;
        while (atomicAdd(&g_bar, 0u) < target) { __nanosleep(64); }
    }
    __syncthreads();
}

__global__ void __launch_bounds__(256) k_lstm_all()
{
    constexpr int BM = 256, BN = 32;
    constexpr int ALOo = BM*80, BHIo = BM*160, BLOo = BM*160 + BN*80;
    constexpr int BUFSZ = (BM + BN) * 160;
    extern __shared__ char smem[];
    uint32_t sbase = smem_u32(smem);
    int tid = threadIdx.x, lane = tid & 31, wid = tid >> 5;
    int wm = wid;
    int bid = blockIdx.x;
    int z = bid % NZL, my = bid / NZL;
    int m0 = my * 256;
    const int nk = 47;
    int ks0 = z * 8, ks1 = min(nk, ks0 + 8);

    const char* asrc[8]; uint32_t adst[8];
    #pragma unroll
    for (int s = 0; s < 8; s++) {
        int g = tid + s * 256;
        int half = (g >= BM * 4);
        int g2 = g - half * BM * 4;
        int row = g2 >> 2, seg = g2 & 3;
        const __nv_bfloat16* base = half ? d_whh_l : d_whh_h;
        asrc[s] = (const char*)(base + (size_t)(m0 + row) * KP_H + seg * 8);
        adst[s] = half * ALOo + row * 80 + seg * 16;
    }
    bool bact = (tid < 128);
    int brow = tid >> 2, bsegc = tid & 3;
    const float4 f4z = make_float4(0.f,0.f,0.f,0.f);

    uint32_t aoff[2], boff[4];
    #pragma unroll
    for (int mt = 0; mt < 2; mt++)
        aoff[mt] = (uint32_t)(((wm*32 + mt*16 + (lane & 15)) * 40 + ((lane >> 4) & 1) * 8) * 2);
    #pragma unroll
    for (int nt = 0; nt < 4; nt++)
        boff[nt] = (uint32_t)(((nt*8 + (lane & 7)) * 40 + ((lane >> 3) & 1) * 8) * 2);

    float* gp = d_gpart6[z];

    for (int t = 0; t < 32; t++) {
        const float* hprev = d_h[t & 1];
        const float* bpf = hprev + (size_t)brow * HH;
        float4 sb0 = f4z, sb1 = f4z;

        auto cpa_pre = [&](int ik, uint32_t bufo) {
            #pragma unroll
            for (int s = 0; s < 8; s++) cpa16(sbase + bufo + adst[s], asrc[s] + (size_t)ik * 64);
        };
        auto load_b = [&](int ik) {
            if (!bact) return;
            int gk = ik * 32 + bsegc * 8;
            sb0 = (gk < HH)     ? __ldcg((const float4*)(bpf + gk))     : f4z;
            sb1 = (gk + 4 < HH) ? __ldcg((const float4*)(bpf + gk + 4)) : f4z;
        };
        auto store_b = [&](char* buf) {
            if (!bact) return;
            uint4 H, L; conv8(sb0, sb1, H, L);
            *(uint4*)(buf + BHIo + brow*80 + bsegc*16) = H;
            *(uint4*)(buf + BLOo + brow*80 + bsegc*16) = L;
        };

        float acc[2][4][4];
        #pragma unroll
        for (int mt = 0; mt < 2; mt++)
            #pragma unroll
            for (int nt = 0; nt < 4; nt++)
                #pragma unroll
                for (int q = 0; q < 4; q++) acc[mt][nt][q] = 0.f;

        cpa_pre(ks0, 0); CPA_COMMIT();
        load_b(ks0); store_b(smem);
        for (int i = ks0; i < ks1; i++) {
            bool more = (i + 1 < ks1);
            if (more) { cpa_pre(i + 1, ((i + 1 - ks0) & 1) * BUFSZ); CPA_COMMIT(); load_b(i + 1); }
            if (more) CPA_WAITN(1); else CPA_WAITN(0);
            __syncthreads();
            uint32_t tb = sbase + ((i - ks0) & 1) * BUFSZ;
            #pragma unroll
            for (int kh = 0; kh < 2; kh++) {
                uint32_t ah[2][4], al[2][4], bh[4][2], bl[4][2];
                #pragma unroll
                for (int mt = 0; mt < 2; mt++) {
                    ldsm4(ah[mt], tb + aoff[mt] + kh*32);
                    ldsm4(al[mt], tb + ALOo + aoff[mt] + kh*32);
                }
                #pragma unroll
                for (int nt = 0; nt < 4; nt++) {
                    ldsm2(bh[nt], tb + BHIo + boff[nt] + kh*32);
                    ldsm2(bl[nt], tb + BLOo + boff[nt] + kh*32);
                }
                #pragma unroll
                for (int mt = 0; mt < 2; mt++)
                    #pragma unroll
                    for (int nt = 0; nt < 4; nt++) {
                        mma16816(acc[mt][nt], ah[mt], bh[nt]);
                        mma16816(acc[mt][nt], ah[mt], bl[nt]);
                        mma16816(acc[mt][nt], al[mt], bh[nt]);
                    }
            }
            if (more) store_b(smem + ((i + 1 - ks0) & 1) * BUFSZ);
            __syncthreads();
        }

        #pragma unroll
        for (int mt = 0; mt < 2; mt++)
            #pragma unroll
            for (int half = 0; half < 2; half++) {
                int gm = m0 + wm*32 + mt*16 + (lane >> 2) + half*8;
                #pragma unroll
                for (int nt = 0; nt < 4; nt++) {
                    int gn = nt*8 + (lane & 3) * 2;
                    *(float2*)(gp + (size_t)gm * 32 + gn) =
                        make_float2(acc[mt][nt][half*2+0], acc[mt][nt][half*2+1]);
                }
            }

        gridbar(144);

        // combine: 2 elements per thread (same j, adjacent b), fast gate math
        float* hnext = d_h[(t + 1) & 1];
        for (int e2i = bid * 256 + tid; e2i < BB * HH / 2; e2i += 144 * 256) {
            int e = e2i * 2;
            int j = e >> 5, b = e & 31;   // b even
            float2 g[4];
            #pragma unroll
            for (int gg = 0; gg < 4; gg++) {
                int r = gg * HH + j;
                float2 v = *(const float2*)&d_xp[(size_t)r * MNB + t * 32 + b];
                float bs = d_bsum[r];
                v.x += bs; v.y += bs;
                #pragma unroll
                for (int zz = 0; zz < NZL; zz++) {
                    float2 p = __ldcg((const float2*)&d_gpart6[zz][(size_t)r * 32 + b]);
                    v.x += p.x; v.y += p.y;
                }
                g[gg] = v;
            }
            float2 cold = *(const float2*)&d_cT[e];
            float ci0 = fsigmoid(g[0].x), ci1 = fsigmoid(g[0].y);
            float cf0 = fsigmoid(g[1].x), cf1 = fsigmoid(g[1].y);
            float cg0 = ftanh(g[2].x),    cg1 = ftanh(g[2].y);
            float co0 = fsigmoid(g[3].x), co1 = fsigmoid(g[3].y);
            float2 cn = make_float2(cf0 * cold.x + ci0 * cg0, cf1 * cold.y + ci1 * cg1);
            *(float2*)&d_cT[e] = cn;
            hnext[b * HH + j]       = co0 * ftanh(cn.x);
            hnext[(b + 1) * HH + j] = co1 * ftanh(cn.y);
        }

        gridbar(144);
    }
}

// ---------------- sort ----------------
__global__ void k_sort(const float* __restrict__ x) {
    int tid = blockIdx.x * blockDim.x + threadIdx.x;
    int b = tid >> 8, e = tid & 255;
    float v[32];
    #pragma unroll
    for (int t = 0; t < 32; t++) v[t] = x[(b * 32 + t) * EE + e];
    for (int a = 1; a < 32; a++) {
        float key = v[a];
        int c = a - 1;
        while (c >= 0 && v[c] > key) { v[c + 1] = v[c]; c--; }
        v[c + 1] = key;
    }
    #pragma unroll
    for (int t = 0; t < 32; t++) {
        unsigned hh, ll; bsplit(v[t], hh, ll);
        size_t idx = (size_t)(t * 32 + b) * KP_E + e;
        d_S_h[idx] = __ushort_as_bfloat16((unsigned short)hh);
        d_S_l[idx] = __ushort_as_bfloat16((unsigned short)ll);
    }
}

// ---------------- vectorized f32 -> hi/lo padded converter ----------------
__global__ void k_conv(const float* __restrict__ src, int ld, int Mr, int Kr,
                       __nv_bfloat16* __restrict__ h, __nv_bfloat16* __restrict__ l,
                       int Kp, long total)
{
    long idx8 = ((long)blockIdx.x * 256 + threadIdx.x) * 8;
    if (idx8 >= total) return;
    int r = (int)(idx8 / Kp), c = (int)(idx8 - (long)r * Kp);
    uint4 H, L;
    if (r < Mr && c + 7 < Kr) {
        const float* p = src + (size_t)r * ld + c;
        conv8(*(const float4*)p, *(const float4*)(p + 4), H, L);
    } else {
        float v[8];
        #pragma unroll
        for (int i = 0; i < 8; i++) {
            int cc = c + i;
            v[i] = (r < Mr && cc < Kr) ? src[(size_t)r * ld + cc] : 0.f;
        }
        conv8(make_float4(v[0],v[1],v[2],v[3]), make_float4(v[4],v[5],v[6],v[7]), H, L);
    }
    *(uint4*)(h + idx8) = H;
    *(uint4*)(l + idx8) = L;
}

// ---------------- init (adds d_bsum) ----------------
__global__ void k_init(const float* __restrict__ q1_w, const float* __restrict__ q1_b,
                       const float* __restrict__ b_ih, const float* __restrict__ b_hh) {
    int idx = blockIdx.x * blockDim.x + threadIdx.x;
    if (idx < PP) {
        int p = idx, i = 0, cnt = 31;
        while (p >= cnt) { p -= cnt; i++; cnt--; }
        d_pi[idx] = i; d_pj[idx] = i + 1 + p;
    } else if (idx < PP + Q1S) {
        int o = idx - PP;
        float s = q1_b[o];
        for (int d = 1; d < 2 * EE; d += 2) s += q1_w[o * (2 * EE) + d];
        d_q1beff[o] = s;
    } else if (idx < PP + Q1S + G4) {
        int r = idx - (PP + Q1S);
        d_bsum[r] = b_ih[r] + b_hh[r];
    } else {
        int zz = idx - (PP + Q1S + G4);
        if (zz < BB * HH)           d_h[0][zz] = 0.f;
        else if (zz < 2 * BB * HH)  d_h[1][zz - BB * HH] = 0.f;
        else if (zz < 3 * BB * HH)  d_cT[zz - 2 * BB * HH] = 0.f;
    }
}

// ---------------- pt combine ----------------
__global__ void k_ptcomb(const float* __restrict__ e1_b) {
    int idx = blockIdx.x * blockDim.x + threadIdx.x;
    if (idx >= EV1S * BB) return;
    int n = idx >> 5;
    float v = e1_b[n];
    #pragma unroll
    for (int z = 0; z < 4; z++) v += d_pt4[z][idx];
    d_ptT[idx] = v;
}

// ---------------- tail: e3 + e4 ----------------
__global__ void k_tail(const float* __restrict__ e3w, const float* __restrict__ e3b,
                       const float* __restrict__ e4w, const float* __restrict__ e4b,
                       float* __restrict__ out)
{
    __shared__ float s2[64][101];
    __shared__ float sw[10][100];
    __shared__ float sb[10], s4[10];
    __shared__ float s4b;
    int m0 = blockIdx.x * 64;
    int tid = threadIdx.x;
    for (int l = 0; l < 100; l++) {
        int idx = tid + l * 64;
        s2[idx / 100][idx % 100] = d_e2buf[(size_t)m0 * EV2S + idx];
    }
    if (tid < 10) { sb[tid] = e3b[tid]; s4[tid] = e4w[tid]; }
    if (tid == 0) s4b = e4b[0];
    for (int l = tid; l < 1000; l += 64) sw[l / 100][l % 100] = e3w[l];
    __syncthreads();
    float acc = s4b;
    #pragma unroll
    for (int g = 0; g < 10; g++) {
        float a = sb[g];
        #pragma unroll 4
        for (int k = 0; k < 100; k++) a = fmaf(s2[tid][k], sw[g][k], a);
        acc = fmaf(fmaxf(a, 0.f), s4[g], acc);
    }
    out[m0 + tid] = fmaxf(acc, 0.f);
}

// ---------------- launch (R13 schedule) ----------------
#define SM42 ((128+64)*160*2)
#define SM81 ((256+32)*160*2)
#define SM512 (40960*3)

extern "C" void kernel_launch(void* const* d_in, const int* in_sizes, int n_in,
                              void* d_out, int out_size)
{
    const float* x    = (const float*)d_in[0];
    const float* w_ih = (const float*)d_in[1];
    const float* w_hh = (const float*)d_in[2];
    const float* b_ih = (const float*)d_in[3];
    const float* b_hh = (const float*)d_in[4];
    const float* q1_w = (const float*)d_in[5];
    const float* q1_b = (const float*)d_in[6];
    const float* q2_w = (const float*)d_in[7];
    const float* q2_b = (const float*)d_in[8];
    const float* e1_w = (const float*)d_in[9];
    const float* e1_b = (const float*)d_in[10];
    const float* e2_w = (const float*)d_in[11];
    const float* e2_b = (const float*)d_in[12];
    const float* e3_w = (const float*)d_in[13];
    const float* e3_b = (const float*)d_in[14];
    const float* e4_w = (const float*)d_in[15];
    const float* e4_b = (const float*)d_in[16];
    float* out = (float*)d_out;

    static cudaStream_t s2s = nullptr;
    static cudaEvent_t evFork = nullptr, evJoin = nullptr;
    static bool inited = false;
    if (!inited) {
        cudaStreamCreateWithFlags(&s2s, cudaStreamNonBlocking);
        cudaEventCreateWithFlags(&evFork, cudaEventDisableTiming);
        cudaEventCreateWithFlags(&evJoin, cudaEventDisableTiming);
        cudaFuncSetAttribute((const void*)tgemm512,        cudaFuncAttributeMaxDynamicSharedMemorySize, SM512);
        cudaFuncSetAttribute((const void*)tgemm2<2,1,4,2>, cudaFuncAttributeMaxDynamicSharedMemorySize, SM42);
        cudaFuncSetAttribute((const void*)tgemm2<1,0,8,1>, cudaFuncAttributeMaxDynamicSharedMemorySize, SM81);
        cudaFuncSetAttribute((const void*)k_lstm_all,      cudaFuncAttributeMaxDynamicSharedMemorySize, SM81);
        inited = true;
    }

    float *pXp, *pH0, *pPt4, *pPt, *pQb, *pAq, *pBq, *pE2;
    __nv_bfloat16 *pWih_h,*pWih_l,*pS_h,*pS_l,*pX_h,*pX_l,*pQ1A_h,*pQ1A_l,*pQ1B_h,*pQ1B_l;
    __nv_bfloat16 *pQ2w_h,*pQ2w_l,*pE1H_h,*pE1H_l,*pE1Q_h,*pE1Q_l,*pE2w_h,*pE2w_l;
    __nv_bfloat16 *pWhh_h,*pWhh_l,*pQ2o_h,*pQ2o_l,*pE1o_h,*pE1o_l;
    cudaGetSymbolAddress((void**)&pXp,  d_xp);
    cudaGetSymbolAddress((void**)&pH0,  d_h);
    cudaGetSymbolAddress((void**)&pPt4, d_pt4);
    cudaGetSymbolAddress((void**)&pPt,  d_ptT);
    cudaGetSymbolAddress((void**)&pQb,  d_q1beff);
    cudaGetSymbolAddress((void**)&pAq,  d_Aq);
    cudaGetSymbolAddress((void**)&pBq,  d_Bq);
    cudaGetSymbolAddress((void**)&pE2,  d_e2buf);
    cudaGetSymbolAddress((void**)&pWih_h, d_wih_h); cudaGetSymbolAddress((void**)&pWih_l, d_wih_l);
    cudaGetSymbolAddress((void**)&pS_h,  d_S_h);    cudaGetSymbolAddress((void**)&pS_l,  d_S_l);
    cudaGetSymbolAddress((void**)&pX_h,  d_x_h);    cudaGetSymbolAddress((void**)&pX_l,  d_x_l);
    cudaGetSymbolAddress((void**)&pQ1A_h, d_q1wA_h); cudaGetSymbolAddress((void**)&pQ1A_l, d_q1wA_l);
    cudaGetSymbolAddress((void**)&pQ1B_h, d_q1wB_h); cudaGetSymbolAddress((void**)&pQ1B_l, d_q1wB_l);
    cudaGetSymbolAddress((void**)&pQ2w_h, d_q2w_h);  cudaGetSymbolAddress((void**)&pQ2w_l, d_q2w_l);
    cudaGetSymbolAddress((void**)&pE1H_h, d_e1wH_h); cudaGetSymbolAddress((void**)&pE1H_l, d_e1wH_l);
    cudaGetSymbolAddress((void**)&pE1Q_h, d_e1wQ_h); cudaGetSymbolAddress((void**)&pE1Q_l, d_e1wQ_l);
    cudaGetSymbolAddress((void**)&pE2w_h, d_e2w_h);  cudaGetSymbolAddress((void**)&pE2w_l, d_e2w_l);
    cudaGetSymbolAddress((void**)&pWhh_h, d_whh_h);  cudaGetSymbolAddress((void**)&pWhh_l, d_whh_l);
    cudaGetSymbolAddress((void**)&pQ2o_h, d_q2o_h);  cudaGetSymbolAddress((void**)&pQ2o_l, d_q2o_l);
    cudaGetSymbolAddress((void**)&pE1o_h, d_e1o_h);  cudaGetSymbolAddress((void**)&pE1o_l, d_e1o_l);

    // ---- main: sort + init ----
    k_sort<<<32, 256>>>(x);
    k_init<<<(PP + Q1S + G4 + 3 * BB * HH + 255) / 256, 256>>>(q1_w, q1_b, b_ih, b_hh);

    cudaEventRecord(evFork, 0);
    cudaStreamWaitEvent(s2s, evFork, 0);

    // ---- side stream: pair-query chain ----
    k_conv<<<(int)(((long)MNB*KP_E/8 + 255)/256), 256, 0, s2s>>>(x, EE, MNB, EE, pX_h, pX_l, KP_E, (long)MNB*KP_E);
    k_conv<<<(int)(((long)640*KP_E/8 + 255)/256), 256, 0, s2s>>>(q1_w, 2*EE, Q1S, EE, pQ1A_h, pQ1A_l, KP_E, (long)640*KP_E);
    k_conv<<<(int)(((long)640*KP_E/8 + 255)/256), 256, 0, s2s>>>(q1_w+EE, 2*EE, Q1S, EE, pQ1B_h, pQ1B_l, KP_E, (long)640*KP_E);
    k_conv<<<(int)(((long)320*KP_Q1/8 + 255)/256), 256, 0, s2s>>>(q2_w, Q1S, QS, Q1S, pQ2w_h, pQ2w_l, KP_Q1, (long)320*KP_Q1);
    tgemm512<<<dim3(5, 8), 512, SM512, s2s>>>(
        pX_h, pX_l, KP_E, pQ1A_h, pQ1A_l, KP_E,
        pQb, nullptr, pAq, nullptr, nullptr, 0, MNB, Q1S, KP_E, 0);
    tgemm512<<<dim3(5, 8), 512, SM512, s2s>>>(
        pX_h, pX_l, KP_E, pQ1B_h, pQ1B_l, KP_E,
        nullptr, nullptr, pBq, nullptr, nullptr, 0, MNB, Q1S, KP_E, 0);
    tgemm2<2,1,4,2><<<dim3(5, 124, 1), 256, SM42, s2s>>>(
        nullptr, nullptr, 0, pQ2w_h, pQ2w_l, KP_Q1, nullptr, 0,
        q2_b, nullptr, nullptr, pQ2o_h, pQ2o_l, KP_Q, MPAIR, QS, Q1S, 1, 0);
    cudaEventRecord(evJoin, s2s);

    // ---- main: LSTM-side + evaluator-weight convs, then xp + LSTM ----
    k_conv<<<(int)(((long)6016*KP_E/8 + 255)/256), 256>>>(w_ih, EE, G4, EE, pWih_h, pWih_l, KP_E, (long)6016*KP_E);
    k_conv<<<(int)(((long)G4P*KP_H/8 + 255)/256), 256>>>(w_hh, HH, G4, HH, pWhh_h, pWhh_l, KP_H, (long)G4P*KP_H);
    k_conv<<<(int)(((long)1024*KP_H/8 + 255)/256), 256>>>(e1_w, HH+QS, EV1S, HH, pE1H_h, pE1H_l, KP_H, (long)1024*KP_H);
    k_conv<<<(int)(((long)1024*KP_Q/8 + 255)/256), 256>>>(e1_w+HH, HH+QS, EV1S, QS, pE1Q_h, pE1Q_l, KP_Q, (long)1024*KP_Q);
    k_conv<<<(int)(((long)128*KP_E2/8 + 255)/256), 256>>>(e2_w, EV1S, EV2S, EV1S, pE2w_h, pE2w_l, KP_E2, (long)128*KP_E2);

    tgemm512<<<dim3(8, 47), 512, SM512>>>(
        pWih_h, pWih_l, KP_E, pS_h, pS_l, KP_E,
        nullptr, nullptr, pXp, nullptr, nullptr, 0, G4, MNB, KP_E, 0);

    k_lstm_all<<<144, 256, SM81>>>();

    // pt partials + combine
    tgemm2<1,0,8,1><<<dim3(1, 4, 4), 256, SM81>>>(
        pE1H_h, pE1H_l, KP_H, nullptr, nullptr, 0, pH0, HH,
        nullptr, nullptr, pPt4, nullptr, nullptr, 0, EV1S, BB, HH, 0, (long)PTP * BB);
    k_ptcomb<<<(EV1S * BB + 255) / 256, 256>>>(e1_b);

    // join side chain, then evaluator chain
    cudaStreamWaitEvent(0, evJoin, 0);

    tgemm512<<<dim3(8, 124), 512, SM512>>>(
        pQ2o_h, pQ2o_l, KP_Q, pE1Q_h, pE1Q_l, KP_Q,
        nullptr, pPt, nullptr, pE1o_h, pE1o_l, KP_E2, MPAIR, EV1S, KP_Q, 1);

    tgemm512<<<dim3(1, 124), 512, SM512>>>(
        pE1o_h, pE1o_l, KP_E2, pE2w_h, pE2w_l, KP_E2,
        e2_b, nullptr, pE2, nullptr, nullptr, 0, MPAIR, EV2S, KP_E2, 1);

    k_tail<<<MPAIR / 64, 64>>>(e3_w, e3_b, e4_w, e4_b, out);
}